// round 4
// baseline (speedup 1.0000x reference)
#include <cuda_runtime.h>
#include <cstdint>

// Problem constants
#define SEQ   2048
#define BATCH 2
#define DIM   1024
#define NH    16
#define HD    64
#define MTOK  (SEQ * BATCH)   // 4096 tokens

// Scratch buffers (allocation-free rule: __device__ globals)
__device__ float g_q[MTOK * DIM];
__device__ float g_k[MTOK * DIM];
__device__ float g_v[MTOK * DIM];
__device__ float g_x[MTOK * DIM];

// ===========================================================================
// Helpers (family-safe PTX only: cp.async, mma.sync tf32, f32x2 packed math)
// ===========================================================================
__device__ __forceinline__ uint32_t sm_u32(const void* p) {
    return (uint32_t)__cvta_generic_to_shared(p);
}
__device__ __forceinline__ void cp_async16(uint32_t smem_addr, const void* gptr) {
    asm volatile("cp.async.cg.shared.global [%0], [%1], 16;" :: "r"(smem_addr), "l"(gptr) : "memory");
}
#define CP_COMMIT() asm volatile("cp.async.commit_group;" ::: "memory")
#define CP_WAIT1()  asm volatile("cp.async.wait_group 1;" ::: "memory")

__device__ __forceinline__ uint32_t f2tf32(float x) {
    uint32_t r;
    asm("cvt.rna.tf32.f32 %0, %1;" : "=r"(r) : "f"(x));
    return r;
}
// D += A@B, m16n8k8 tf32
__device__ __forceinline__ void mma_tf32(float* c, const uint32_t* a, const uint32_t* b) {
    asm volatile(
        "mma.sync.aligned.m16n8k8.row.col.f32.tf32.tf32.f32 "
        "{%0,%1,%2,%3}, {%4,%5,%6,%7}, {%8,%9}, {%0,%1,%2,%3};"
        : "+f"(c[0]), "+f"(c[1]), "+f"(c[2]), "+f"(c[3])
        : "r"(a[0]), "r"(a[1]), "r"(a[2]), "r"(a[3]), "r"(b[0]), "r"(b[1]));
}

// ---- packed f32x2 (Blackwell family, SASS FFMA2) ----
typedef unsigned long long ull;
__device__ __forceinline__ ull dup2(float x) {
    ull r;
    asm("mov.b64 %0, {%1, %1};" : "=l"(r) : "f"(x));
    return r;
}
__device__ __forceinline__ void fma2(ull& d, ull a, ull b) {
    asm("fma.rn.f32x2 %0, %1, %2, %0;" : "+l"(d) : "l"(a), "l"(b));
}
__device__ __forceinline__ ull mul2(ull a, ull b) {
    ull r;
    asm("mul.rn.f32x2 %0, %1, %2;" : "=l"(r) : "l"(a), "l"(b));
    return r;
}
__device__ __forceinline__ float lo2(ull v) { return __uint_as_float((uint32_t)v); }
__device__ __forceinline__ float hi2(ull v) { return __uint_as_float((uint32_t)(v >> 32)); }

// ===========================================================================
// tf32 tensor-core GEMM with 2-term X-side split (kills X rounding error):
//   Y[M,N] = (Xh + Xl) @ W_tf32^T + bias,  Xh = rna(X), Xl = rna(X - Xh)
// CTA tile 128x128, 8 warps (each 64x32), K-chunk 32, 2-stage cp.async.
// ===========================================================================
#define GSTAGES      2
#define SM_PITCH     36
#define AFLOATS      (128 * SM_PITCH)
#define STAGE_FLOATS (2 * AFLOATS)
#define GEMM_DSMEM   (GSTAGES * STAGE_FLOATS * 4)   // 73728 bytes

__global__ __launch_bounds__(256, 2)
void gemm_mma_kernel(const float* __restrict__ X, const float* __restrict__ W,
                     const float* __restrict__ bias, float* __restrict__ Y)
{
    extern __shared__ float sm[];
    const int K = DIM, N = DIM;

    const int tid  = threadIdx.x;
    const int wid  = tid >> 5;
    const int lane = tid & 31;
    const int bm   = blockIdx.y;
    const int bn   = blockIdx.x;

    const int qd = tid & 7;
    const int r0 = tid >> 3;

    auto load_chunk = [&](int st, int c) {
        float* As = sm + st * STAGE_FLOATS;
        float* Bs = As + AFLOATS;
        const int k0 = c * 32;
        const float* xp = X + (size_t)(bm * 128 + r0) * K + k0 + qd * 4;
        const float* wp = W + (size_t)(bn * 128 + r0) * K + k0 + qd * 4;
#pragma unroll
        for (int i = 0; i < 4; i++) {
            const int r = r0 + 32 * i;
            cp_async16(sm_u32(&As[r * SM_PITCH + qd * 4]), xp + (size_t)(32 * i) * K);
            cp_async16(sm_u32(&Bs[r * SM_PITCH + qd * 4]), wp + (size_t)(32 * i) * K);
        }
        CP_COMMIT();
    };

    load_chunk(0, 0);
    load_chunk(1, 1);

    const int wm = (wid & 1) * 64;
    const int wn = (wid >> 1) * 32;
    const int g  = lane >> 2;
    const int t  = lane & 3;

    float acc[4][4][4];
#pragma unroll
    for (int mt = 0; mt < 4; mt++)
#pragma unroll
        for (int nt = 0; nt < 4; nt++)
#pragma unroll
            for (int e = 0; e < 4; e++) acc[mt][nt][e] = 0.f;

    for (int c = 0; c < 32; c++) {
        const int st = c & 1;
        CP_WAIT1();
        __syncthreads();

        const float* As = sm + st * STAGE_FLOATS;
        const float* Bs = As + AFLOATS;

#pragma unroll
        for (int ks = 0; ks < 4; ks++) {
            const int k0 = ks * 8;
            uint32_t b[4][2];
#pragma unroll
            for (int nt = 0; nt < 4; nt++) {
                const float* bp = &Bs[(wn + nt * 8 + g) * SM_PITCH + k0 + t];
                b[nt][0] = f2tf32(bp[0]);
                b[nt][1] = f2tf32(bp[4]);
            }
#pragma unroll
            for (int mt = 0; mt < 4; mt++) {
                const float* ap = &As[(wm + mt * 16 + g) * SM_PITCH + k0 + t];
                float x0 = ap[0], x1 = ap[8 * SM_PITCH], x2 = ap[4], x3 = ap[8 * SM_PITCH + 4];
                uint32_t ah[4], al[4];
                ah[0] = f2tf32(x0); al[0] = f2tf32(x0 - __uint_as_float(ah[0]));
                ah[1] = f2tf32(x1); al[1] = f2tf32(x1 - __uint_as_float(ah[1]));
                ah[2] = f2tf32(x2); al[2] = f2tf32(x2 - __uint_as_float(ah[2]));
                ah[3] = f2tf32(x3); al[3] = f2tf32(x3 - __uint_as_float(ah[3]));
#pragma unroll
                for (int nt = 0; nt < 4; nt++) mma_tf32(acc[mt][nt], ah, b[nt]);
#pragma unroll
                for (int nt = 0; nt < 4; nt++) mma_tf32(acc[mt][nt], al, b[nt]);
            }
        }

        __syncthreads();
        const int cn = c + GSTAGES;
        if (cn < 32) load_chunk(st, cn);
        else         CP_COMMIT();
    }

#pragma unroll
    for (int mt = 0; mt < 4; mt++) {
        const int row = bm * 128 + wm + mt * 16 + g;
#pragma unroll
        for (int nt = 0; nt < 4; nt++) {
            const int col = bn * 128 + wn + nt * 8 + 2 * t;
            float2 bi = *(const float2*)&bias[col];
            float2 r01, r23;
            r01.x = acc[mt][nt][0] + bi.x;
            r01.y = acc[mt][nt][1] + bi.y;
            r23.x = acc[mt][nt][2] + bi.x;
            r23.y = acc[mt][nt][3] + bi.y;
            *(float2*)&Y[(size_t)row * N + col]       = r01;
            *(float2*)&Y[(size_t)(row + 8) * N + col] = r23;
        }
    }
}

// ===========================================================================
// Flash attention, fp32 numerics via packed f32x2 FMA (FFMA2).
// Block = 128 query rows x one (b,h); streams 64-key tiles.
// Thread tile 8 rows x 4 cols, rows packed in f32x2 pairs.
// Layouts: Qs[d][row] (row-pairs contiguous), Ks[d][key], Vs[key][d],
//          Ss[key][row] (TRANSPOSED: prob row-pairs contiguous for PV).
// ===========================================================================
#define ATN_BM 128
#define ATN_BN 64
#define QS_OFF 0
#define KS_OFF (64 * 132)                       // 8448
#define VS_OFF (KS_OFF + 64 * 68)               // 12800
#define SS_OFF (VS_OFF + 64 * 68)               // 17152
#define MS_OFF (SS_OFF + 64 * 132)              // 25600
#define LS_OFF (MS_OFF + 128)
#define AS_OFF (LS_OFF + 128)
#define ATTN_SMEM_FLOATS (AS_OFF + 128)         // 25984 -> 103936 B

__global__ __launch_bounds__(256, 2)
void attn_kernel(const float* __restrict__ q, const float* __restrict__ k,
                 const float* __restrict__ v, float* __restrict__ xout)
{
    extern __shared__ float sm[];
    float* Qs  = sm + QS_OFF;
    float* Ks  = sm + KS_OFF;
    float* Vs  = sm + VS_OFF;
    float* Ss  = sm + SS_OFF;
    float* m_s = sm + MS_OFF;
    float* l_s = sm + LS_OFF;
    float* a_s = sm + AS_OFF;

    const int tid = threadIdx.x;
    const int qt  = blockIdx.x;            // 0..15
    const int bh  = blockIdx.y;            // b*H + h
    const int bb  = bh >> 4;
    const int hh  = bh & 15;
    const size_t head_off = (size_t)bb * DIM + (size_t)hh * HD;
    const size_t rs = (size_t)BATCH * DIM;   // 2048

    // ---- load Q tile (transposed: Qs[d][row]) ----
    {
        const int lr = tid >> 1;             // 0..127
        const int ld = (tid & 1) * 32;       // 0 or 32
        const float* qp = q + (size_t)(qt * ATN_BM + lr) * rs + head_off + ld;
#pragma unroll
        for (int u = 0; u < 32; u += 4) {
            float4 t = *(const float4*)(qp + u);
            Qs[(ld + u + 0) * 132 + lr] = t.x;
            Qs[(ld + u + 1) * 132 + lr] = t.y;
            Qs[(ld + u + 2) * 132 + lr] = t.z;
            Qs[(ld + u + 3) * 132 + lr] = t.w;
        }
    }
    if (tid < 128) { m_s[tid] = -1e30f; l_s[tid] = 0.f; }

    const int ty = tid >> 4;   // 0..15 -> rows ty*8 .. ty*8+7
    const int tx = tid & 15;   // 0..15 -> cols tx*4 .. tx*4+3

    ull o2[4][4];              // [row-pair][col] packed over rows
#pragma unroll
    for (int ip = 0; ip < 4; ip++)
#pragma unroll
        for (int jc = 0; jc < 4; jc++) o2[ip][jc] = 0ull;

    for (int kt = 0; kt < SEQ / ATN_BN; kt++) {
        __syncthreads();
        // ---- load K (transposed Ks[d][key]) and V (natural Vs[key][d]) ----
        {
            const int lr = tid >> 2;          // 0..63
            const int ld = (tid & 3) * 16;
            const float* kp = k + (size_t)(kt * ATN_BN + lr) * rs + head_off + ld;
            const float* vp = v + (size_t)(kt * ATN_BN + lr) * rs + head_off + ld;
#pragma unroll
            for (int u = 0; u < 16; u += 4) {
                float4 t = *(const float4*)(kp + u);
                Ks[(ld + u + 0) * 68 + lr] = t.x;
                Ks[(ld + u + 1) * 68 + lr] = t.y;
                Ks[(ld + u + 2) * 68 + lr] = t.z;
                Ks[(ld + u + 3) * 68 + lr] = t.w;
                *(float4*)&Vs[lr * 68 + ld + u] = *(const float4*)(vp + u);
            }
        }
        __syncthreads();

        // ---- S = Q @ K^T  (packed rows; a-pairs load direct from Qs) ----
        ull s2[4][4];
#pragma unroll
        for (int ip = 0; ip < 4; ip++)
#pragma unroll
            for (int jc = 0; jc < 4; jc++) s2[ip][jc] = 0ull;

#pragma unroll 4
        for (int dd = 0; dd < HD; dd++) {
            ulonglong2 aA = *(const ulonglong2*)&Qs[dd * 132 + ty * 8];
            ulonglong2 aB = *(const ulonglong2*)&Qs[dd * 132 + ty * 8 + 4];
            ull a2[4] = {aA.x, aA.y, aB.x, aB.y};
            float4 kv = *(const float4*)&Ks[dd * 68 + tx * 4];
            ull b2[4] = {dup2(kv.x), dup2(kv.y), dup2(kv.z), dup2(kv.w)};
#pragma unroll
            for (int ip = 0; ip < 4; ip++)
#pragma unroll
                for (int jc = 0; jc < 4; jc++)
                    fma2(s2[ip][jc], a2[ip], b2[jc]);
        }
        // store transposed: Ss[key][row]
#pragma unroll
        for (int jc = 0; jc < 4; jc++)
#pragma unroll
            for (int ip = 0; ip < 4; ip++)
                *(ull*)&Ss[(tx * 4 + jc) * 132 + ty * 8 + 2 * ip] = s2[ip][jc];
        __syncthreads();

        // ---- online softmax: 2 threads per row (shfl pair reduce) ----
        {
            const int r   = tid >> 1;
            const int seg = tid & 1;
            float mx = -1e30f;
#pragma unroll 8
            for (int jj = 0; jj < 32; jj++)
                mx = fmaxf(mx, Ss[(seg * 32 + jj) * 132 + r]);
            mx = fmaxf(mx, __shfl_xor_sync(0xffffffffu, mx, 1));
            float mold = m_s[r];
            float mnew = fmaxf(mold, mx);
            float sum = 0.f;
#pragma unroll 8
            for (int jj = 0; jj < 32; jj++) {
                const int idx = (seg * 32 + jj) * 132 + r;
                float p = __expf(Ss[idx] - mnew);
                Ss[idx] = p;
                sum += p;
            }
            sum += __shfl_xor_sync(0xffffffffu, sum, 1);
            __syncwarp();   // all reads of m_s/l_s done before leader writes
            if (seg == 0) {
                float alpha = __expf(mold - mnew);
                l_s[r] = l_s[r] * alpha + sum;
                m_s[r] = mnew;
                a_s[r] = alpha;
            }
        }
        __syncthreads();

        // ---- rescale O, accumulate P @ V (prob row-pairs direct from Ss) ----
#pragma unroll
        for (int ip = 0; ip < 4; ip++) {
            ull al2 = *(const ull*)&a_s[ty * 8 + 2 * ip];
#pragma unroll
            for (int jc = 0; jc < 4; jc++) o2[ip][jc] = mul2(o2[ip][jc], al2);
        }
#pragma unroll 2
        for (int jk = 0; jk < ATN_BN; jk++) {
            ulonglong2 pA = *(const ulonglong2*)&Ss[jk * 132 + ty * 8];
            ulonglong2 pB = *(const ulonglong2*)&Ss[jk * 132 + ty * 8 + 4];
            ull p2[4] = {pA.x, pA.y, pB.x, pB.y};
            float4 vv = *(const float4*)&Vs[jk * 68 + tx * 4];
            ull v2[4] = {dup2(vv.x), dup2(vv.y), dup2(vv.z), dup2(vv.w)};
#pragma unroll
            for (int ip = 0; ip < 4; ip++)
#pragma unroll
                for (int jc = 0; jc < 4; jc++)
                    fma2(o2[ip][jc], p2[ip], v2[jc]);
        }
    }

    // ---- normalize and write out ----
#pragma unroll
    for (int ip = 0; ip < 4; ip++) {
        const float l0 = l_s[ty * 8 + 2 * ip];
        const float l1 = l_s[ty * 8 + 2 * ip + 1];
        const float i0 = 1.f / l0, i1 = 1.f / l1;
        float4 r0v, r1v;
        r0v.x = lo2(o2[ip][0]) * i0; r1v.x = hi2(o2[ip][0]) * i1;
        r0v.y = lo2(o2[ip][1]) * i0; r1v.y = hi2(o2[ip][1]) * i1;
        r0v.z = lo2(o2[ip][2]) * i0; r1v.z = hi2(o2[ip][2]) * i1;
        r0v.w = lo2(o2[ip][3]) * i0; r1v.w = hi2(o2[ip][3]) * i1;
        const size_t row0 = (size_t)(qt * ATN_BM + ty * 8 + 2 * ip);
        *(float4*)&xout[row0 * rs + head_off + tx * 4]       = r0v;
        *(float4*)&xout[(row0 + 1) * rs + head_off + tx * 4] = r1v;
    }
}

// ---------------------------------------------------------------------------
// kernel_launch
// ---------------------------------------------------------------------------
extern "C" void kernel_launch(void* const* d_in, const int* in_sizes, int n_in,
                              void* d_out, int out_size)
{
    const float* query = (const float*)d_in[0];
    const float* key   = (const float*)d_in[1];
    const float* value = (const float*)d_in[2];
    const float* Wq    = (const float*)d_in[3];
    const float* bq    = (const float*)d_in[4];
    const float* Wk    = (const float*)d_in[5];
    const float* bk    = (const float*)d_in[6];
    const float* Wv    = (const float*)d_in[7];
    const float* bv    = (const float*)d_in[8];
    const float* Wo    = (const float*)d_in[9];
    const float* bo    = (const float*)d_in[10];
    float* out = (float*)d_out;

    float *qb, *kb, *vb, *xb;
    cudaGetSymbolAddress((void**)&qb, g_q);
    cudaGetSymbolAddress((void**)&kb, g_k);
    cudaGetSymbolAddress((void**)&vb, g_v);
    cudaGetSymbolAddress((void**)&xb, g_x);

    cudaFuncSetAttribute(gemm_mma_kernel,
                         cudaFuncAttributeMaxDynamicSharedMemorySize, GEMM_DSMEM);
    const int attn_smem = ATTN_SMEM_FLOATS * (int)sizeof(float);   // 103936
    cudaFuncSetAttribute(attn_kernel,
                         cudaFuncAttributeMaxDynamicSharedMemorySize, attn_smem);

    dim3 gemm_grid(DIM / 128, MTOK / 128);   // (8, 32)

    gemm_mma_kernel<<<gemm_grid, 256, GEMM_DSMEM>>>(query, Wq, bq, qb);
    gemm_mma_kernel<<<gemm_grid, 256, GEMM_DSMEM>>>(key,   Wk, bk, kb);
    gemm_mma_kernel<<<gemm_grid, 256, GEMM_DSMEM>>>(value, Wv, bv, vb);

    attn_kernel<<<dim3(SEQ / ATN_BM, BATCH * NH), 256, attn_smem>>>(qb, kb, vb, xb);

    gemm_mma_kernel<<<gemm_grid, 256, GEMM_DSMEM>>>(xb, Wo, bo, out);
}

// round 5
// speedup vs baseline: 1.5993x; 1.5993x over previous
#include <cuda_runtime.h>
#include <cuda_bf16.h>
#include <cstdint>

// Problem constants
#define SEQ   2048
#define BATCH 2
#define DIM   1024
#define NH    16
#define HD    64
#define MTOK  (SEQ * BATCH)   // 4096 tokens
#define NTOT  (MTOK * DIM)    // 4M elements

// Scratch buffers (allocation-free rule: __device__ globals)
__device__ float g_q[NTOT];
__device__ float g_k[NTOT];
__device__ float g_v[NTOT];
__device__ float g_x[NTOT];
// bf16 split scratch
__device__ __nv_bfloat16 g_qh[NTOT];
__device__ __nv_bfloat16 g_ql[NTOT];
__device__ __nv_bfloat16 g_kh[NTOT];
__device__ __nv_bfloat16 g_kl[NTOT];
__device__ __nv_bfloat16 g_vth[NTOT];   // per-(b,h) transposed: [bh][d][s]
__device__ __nv_bfloat16 g_vtl[NTOT];

// ===========================================================================
// Helpers (family-safe PTX only: cp.async, mma.sync, no tcgen05)
// ===========================================================================
__device__ __forceinline__ uint32_t sm_u32(const void* p) {
    return (uint32_t)__cvta_generic_to_shared(p);
}
__device__ __forceinline__ void cp_async16(uint32_t smem_addr, const void* gptr) {
    asm volatile("cp.async.cg.shared.global [%0], [%1], 16;" :: "r"(smem_addr), "l"(gptr) : "memory");
}
#define CP_COMMIT() asm volatile("cp.async.commit_group;" ::: "memory")
#define CP_WAIT1()  asm volatile("cp.async.wait_group 1;" ::: "memory")

__device__ __forceinline__ uint32_t f2tf32(float x) {
    uint32_t r;
    asm("cvt.rna.tf32.f32 %0, %1;" : "=r"(r) : "f"(x));
    return r;
}
// D += A@B, m16n8k8 tf32
__device__ __forceinline__ void mma_tf32(float* c, const uint32_t* a, const uint32_t* b) {
    asm volatile(
        "mma.sync.aligned.m16n8k8.row.col.f32.tf32.tf32.f32 "
        "{%0,%1,%2,%3}, {%4,%5,%6,%7}, {%8,%9}, {%0,%1,%2,%3};"
        : "+f"(c[0]), "+f"(c[1]), "+f"(c[2]), "+f"(c[3])
        : "r"(a[0]), "r"(a[1]), "r"(a[2]), "r"(a[3]), "r"(b[0]), "r"(b[1]));
}
// D += A@B, m16n8k16 bf16
__device__ __forceinline__ void mma_bf16(float* c, const uint32_t* a, const uint32_t* b) {
    asm volatile(
        "mma.sync.aligned.m16n8k16.row.col.f32.bf16.bf16.f32 "
        "{%0,%1,%2,%3}, {%4,%5,%6,%7}, {%8,%9}, {%0,%1,%2,%3};"
        : "+f"(c[0]), "+f"(c[1]), "+f"(c[2]), "+f"(c[3])
        : "r"(a[0]), "r"(a[1]), "r"(a[2]), "r"(a[3]), "r"(b[0]), "r"(b[1]));
}

// split-pack two floats into bf16x2 high + residual bf16x2 low
__device__ __forceinline__ void packsplit2(float x, float y, uint32_t& h, uint32_t& l) {
    __nv_bfloat162 hb = __float22bfloat162_rn(make_float2(x, y));   // .x = lo half
    h = *reinterpret_cast<uint32_t*>(&hb);
    float rx = x - __low2float(hb);
    float ry = y - __high2float(hb);
    __nv_bfloat162 lb = __float22bfloat162_rn(make_float2(rx, ry));
    l = *reinterpret_cast<uint32_t*>(&lb);
}

// ===========================================================================
// tf32 tensor-core GEMM with 2-term X-side split (unchanged, known-good):
//   Y[M,N] = (Xh + Xl) @ W_tf32^T + bias
// ===========================================================================
#define GSTAGES      2
#define SM_PITCH     36
#define AFLOATS      (128 * SM_PITCH)
#define STAGE_FLOATS (2 * AFLOATS)
#define GEMM_DSMEM   (GSTAGES * STAGE_FLOATS * 4)   // 73728 bytes

__global__ __launch_bounds__(256, 2)
void gemm_mma_kernel(const float* __restrict__ X, const float* __restrict__ W,
                     const float* __restrict__ bias, float* __restrict__ Y)
{
    extern __shared__ float sm[];
    const int K = DIM, N = DIM;

    const int tid  = threadIdx.x;
    const int wid  = tid >> 5;
    const int lane = tid & 31;
    const int bm   = blockIdx.y;
    const int bn   = blockIdx.x;

    const int qd = tid & 7;
    const int r0 = tid >> 3;

    auto load_chunk = [&](int st, int c) {
        float* As = sm + st * STAGE_FLOATS;
        float* Bs = As + AFLOATS;
        const int k0 = c * 32;
        const float* xp = X + (size_t)(bm * 128 + r0) * K + k0 + qd * 4;
        const float* wp = W + (size_t)(bn * 128 + r0) * K + k0 + qd * 4;
#pragma unroll
        for (int i = 0; i < 4; i++) {
            const int r = r0 + 32 * i;
            cp_async16(sm_u32(&As[r * SM_PITCH + qd * 4]), xp + (size_t)(32 * i) * K);
            cp_async16(sm_u32(&Bs[r * SM_PITCH + qd * 4]), wp + (size_t)(32 * i) * K);
        }
        CP_COMMIT();
    };

    load_chunk(0, 0);
    load_chunk(1, 1);

    const int wm = (wid & 1) * 64;
    const int wn = (wid >> 1) * 32;
    const int g  = lane >> 2;
    const int t  = lane & 3;

    float acc[4][4][4];
#pragma unroll
    for (int mt = 0; mt < 4; mt++)
#pragma unroll
        for (int nt = 0; nt < 4; nt++)
#pragma unroll
            for (int e = 0; e < 4; e++) acc[mt][nt][e] = 0.f;

    for (int c = 0; c < 32; c++) {
        const int st = c & 1;
        CP_WAIT1();
        __syncthreads();

        const float* As = sm + st * STAGE_FLOATS;
        const float* Bs = As + AFLOATS;

#pragma unroll
        for (int ks = 0; ks < 4; ks++) {
            const int k0 = ks * 8;
            uint32_t b[4][2];
#pragma unroll
            for (int nt = 0; nt < 4; nt++) {
                const float* bp = &Bs[(wn + nt * 8 + g) * SM_PITCH + k0 + t];
                b[nt][0] = f2tf32(bp[0]);
                b[nt][1] = f2tf32(bp[4]);
            }
#pragma unroll
            for (int mt = 0; mt < 4; mt++) {
                const float* ap = &As[(wm + mt * 16 + g) * SM_PITCH + k0 + t];
                float x0 = ap[0], x1 = ap[8 * SM_PITCH], x2 = ap[4], x3 = ap[8 * SM_PITCH + 4];
                uint32_t ah[4], al[4];
                ah[0] = f2tf32(x0); al[0] = f2tf32(x0 - __uint_as_float(ah[0]));
                ah[1] = f2tf32(x1); al[1] = f2tf32(x1 - __uint_as_float(ah[1]));
                ah[2] = f2tf32(x2); al[2] = f2tf32(x2 - __uint_as_float(ah[2]));
                ah[3] = f2tf32(x3); al[3] = f2tf32(x3 - __uint_as_float(ah[3]));
#pragma unroll
                for (int nt = 0; nt < 4; nt++) mma_tf32(acc[mt][nt], ah, b[nt]);
#pragma unroll
                for (int nt = 0; nt < 4; nt++) mma_tf32(acc[mt][nt], al, b[nt]);
            }
        }

        __syncthreads();
        const int cn = c + GSTAGES;
        if (cn < 32) load_chunk(st, cn);
        else         CP_COMMIT();
    }

#pragma unroll
    for (int mt = 0; mt < 4; mt++) {
        const int row = bm * 128 + wm + mt * 16 + g;
#pragma unroll
        for (int nt = 0; nt < 4; nt++) {
            const int col = bn * 128 + wn + nt * 8 + 2 * t;
            float2 bi = *(const float2*)&bias[col];
            float2 r01, r23;
            r01.x = acc[mt][nt][0] + bi.x;
            r01.y = acc[mt][nt][1] + bi.y;
            r23.x = acc[mt][nt][2] + bi.x;
            r23.y = acc[mt][nt][3] + bi.y;
            *(float2*)&Y[(size_t)row * N + col]       = r01;
            *(float2*)&Y[(size_t)(row + 8) * N + col] = r23;
        }
    }
}

// ===========================================================================
// Prep kernels: bf16 2-term splits
// ===========================================================================
__global__ __launch_bounds__(256)
void split_bf16_kernel(const float* __restrict__ x,
                       __nv_bfloat16* __restrict__ h, __nv_bfloat16* __restrict__ l)
{
    const int i4 = (blockIdx.x * 256 + threadIdx.x) * 4;   // grid covers exactly NTOT
    float4 v = *(const float4*)(x + i4);
    uint32_t h0, l0, h1, l1;
    packsplit2(v.x, v.y, h0, l0);
    packsplit2(v.z, v.w, h1, l1);
    uint2 hh = {h0, h1}, ll = {l0, l1};
    *(uint2*)(h + i4) = hh;
    *(uint2*)(l + i4) = ll;
}

// V transpose + split: v[s][b*1024+h*64+d] -> vth/vtl[(bh*64+d)*2048 + s]
__global__ __launch_bounds__(256)
void vsplit_transpose_kernel(const float* __restrict__ v,
                             __nv_bfloat16* __restrict__ vth,
                             __nv_bfloat16* __restrict__ vtl)
{
    __shared__ float ts[64][65];
    const int st = blockIdx.x;          // s-tile (64 rows)
    const int bh = blockIdx.y;
    const int bb = bh >> 4, hh = bh & 15;
    const int tid = threadIdx.x;

    // load 64 s-rows x 64 d (coalesced)
    {
        const int r  = tid >> 2;
        const int c0 = (tid & 3) * 16;
        const float* src = v + (size_t)(st * 64 + r) * 2048 + bb * 1024 + hh * 64 + c0;
#pragma unroll
        for (int u = 0; u < 16; u += 4) {
            float4 t = *(const float4*)(src + u);
            ts[r][c0 + u + 0] = t.x; ts[r][c0 + u + 1] = t.y;
            ts[r][c0 + u + 2] = t.z; ts[r][c0 + u + 3] = t.w;
        }
    }
    __syncthreads();

    // write transposed: row d, 16 s values per thread
    {
        const int d  = tid >> 2;
        const int s0 = (tid & 3) * 16;
        const size_t base = (size_t)(bh * 64 + d) * 2048 + st * 64 + s0;
#pragma unroll
        for (int u = 0; u < 16; u += 2) {
            uint32_t h2, l2;
            packsplit2(ts[s0 + u][d], ts[s0 + u + 1][d], h2, l2);
            *(uint32_t*)(vth + base + u) = h2;
            *(uint32_t*)(vtl + base + u) = l2;
        }
    }
}

// ===========================================================================
// Flash attention on tensor cores: bf16 3-pass split MMAs, fp32 accum.
// CTA = 128 q-rows x one (b,h); 8 warps x 16 rows; 64-key tiles, cp.async
// double-buffered K/V; softmax entirely in registers (shfl over t-lanes).
// ===========================================================================
#define AT_PITCHB 144                     // 72 bf16 per row (64 + 8 pad)
#define AT_QBYTES (128 * AT_PITCHB)       // 18432 per array
#define AT_TBYTES (64 * AT_PITCHB)        // 9216 per tile array
#define AT_ST0    (2 * AT_QBYTES)         // stage region start (36864)
#define AT_STSZ   (4 * AT_TBYTES)         // KH,KL,VH,VL per stage (36864)
#define AT_SMEM   (AT_ST0 + 2 * AT_STSZ)  // 110592 bytes

__global__ __launch_bounds__(256, 2)
void attn_mma_kernel(const __nv_bfloat16* __restrict__ qh, const __nv_bfloat16* __restrict__ ql,
                     const __nv_bfloat16* __restrict__ kh, const __nv_bfloat16* __restrict__ kl,
                     const __nv_bfloat16* __restrict__ vth, const __nv_bfloat16* __restrict__ vtl,
                     float* __restrict__ xout)
{
    extern __shared__ char smem[];
    const uint32_t sbase = sm_u32(smem);

    const int tid  = threadIdx.x;
    const int wid  = tid >> 5;
    const int lane = tid & 31;
    const int g    = lane >> 2;
    const int t    = lane & 3;
    const int qt   = blockIdx.x;
    const int bh   = blockIdx.y;
    const int bb   = bh >> 4, hh = bh & 15;
    const int ho   = bb * 1024 + hh * 64;        // element offset within token row

    // ---- load Q tiles (group 0) ----
    {
        const int r  = tid >> 1;
        const int c0 = (tid & 1) * 4;
        const __nv_bfloat16* sh = qh + (size_t)(qt * 128 + r) * 2048 + ho + c0 * 8;
        const __nv_bfloat16* sl = ql + (size_t)(qt * 128 + r) * 2048 + ho + c0 * 8;
        const uint32_t dh = sbase + r * AT_PITCHB + c0 * 16;
        const uint32_t dl = dh + AT_QBYTES;
#pragma unroll
        for (int i = 0; i < 4; i++) {
            cp_async16(dh + i * 16, sh + i * 8);
            cp_async16(dl + i * 16, sl + i * 8);
        }
        CP_COMMIT();
    }

    // ---- K/V stage loader: one row per thread ----
    auto load_stage = [&](int s, int kt) {
        const uint32_t stb = sbase + AT_ST0 + s * AT_STSZ;
        const int r     = tid & 63;
        const int which = tid >> 6;             // 0:KH 1:KL 2:VH 3:VL
        const __nv_bfloat16* src;
        if (which == 0)      src = kh  + (size_t)(kt * 64 + r) * 2048 + ho;
        else if (which == 1) src = kl  + (size_t)(kt * 64 + r) * 2048 + ho;
        else if (which == 2) src = vth + (size_t)(bh * 64 + r) * 2048 + kt * 64;
        else                 src = vtl + (size_t)(bh * 64 + r) * 2048 + kt * 64;
        const uint32_t dst = stb + which * AT_TBYTES + r * AT_PITCHB;
#pragma unroll
        for (int i = 0; i < 8; i++) cp_async16(dst + i * 16, src + i * 8);
        CP_COMMIT();
    };

    load_stage(0, 0);
    load_stage(1, 1);

    float m0 = -1e30f, m1 = -1e30f, l0 = 0.f, l1 = 0.f;
    float o[8][4];
#pragma unroll
    for (int nt = 0; nt < 8; nt++)
#pragma unroll
        for (int e = 0; e < 4; e++) o[nt][e] = 0.f;

    const int mrow = wid * 16;
    const char* Qh0 = smem + (mrow + g) * AT_PITCHB + 4 * t;
    const char* Ql0 = Qh0 + AT_QBYTES;

    for (int kt = 0; kt < SEQ / 64; kt++) {
        CP_WAIT1();
        __syncthreads();
        const char* stp = smem + AT_ST0 + (kt & 1) * AT_STSZ;

        // ---- S = Q @ K^T, 3-pass bf16 split ----
        float sc[8][4];
#pragma unroll
        for (int nt = 0; nt < 8; nt++)
#pragma unroll
            for (int e = 0; e < 4; e++) sc[nt][e] = 0.f;

#pragma unroll
        for (int ks = 0; ks < 4; ks++) {
            const int ko = ks * 32;
            uint32_t ah[4], al[4];
            ah[0] = *(const uint32_t*)(Qh0 + ko);
            ah[1] = *(const uint32_t*)(Qh0 + 8 * AT_PITCHB + ko);
            ah[2] = *(const uint32_t*)(Qh0 + ko + 16);
            ah[3] = *(const uint32_t*)(Qh0 + 8 * AT_PITCHB + ko + 16);
            al[0] = *(const uint32_t*)(Ql0 + ko);
            al[1] = *(const uint32_t*)(Ql0 + 8 * AT_PITCHB + ko);
            al[2] = *(const uint32_t*)(Ql0 + ko + 16);
            al[3] = *(const uint32_t*)(Ql0 + 8 * AT_PITCHB + ko + 16);
#pragma unroll
            for (int nt = 0; nt < 8; nt++) {
                const char* kp = stp + (nt * 8 + g) * AT_PITCHB + ko + 4 * t;
                uint32_t bhf[2], blf[2];
                bhf[0] = *(const uint32_t*)kp;
                bhf[1] = *(const uint32_t*)(kp + 16);
                blf[0] = *(const uint32_t*)(kp + AT_TBYTES);
                blf[1] = *(const uint32_t*)(kp + AT_TBYTES + 16);
                mma_bf16(sc[nt], ah, bhf);
                mma_bf16(sc[nt], al, bhf);
                mma_bf16(sc[nt], ah, blf);
            }
        }

        // ---- online softmax in registers (rows g and g+8) ----
        float mx0 = -1e30f, mx1 = -1e30f;
#pragma unroll
        for (int nt = 0; nt < 8; nt++) {
            mx0 = fmaxf(mx0, fmaxf(sc[nt][0], sc[nt][1]));
            mx1 = fmaxf(mx1, fmaxf(sc[nt][2], sc[nt][3]));
        }
        mx0 = fmaxf(mx0, __shfl_xor_sync(0xffffffffu, mx0, 1));
        mx0 = fmaxf(mx0, __shfl_xor_sync(0xffffffffu, mx0, 2));
        mx1 = fmaxf(mx1, __shfl_xor_sync(0xffffffffu, mx1, 1));
        mx1 = fmaxf(mx1, __shfl_xor_sync(0xffffffffu, mx1, 2));
        const float mn0 = fmaxf(m0, mx0), mn1 = fmaxf(m1, mx1);
        const float a0 = __expf(m0 - mn0), a1 = __expf(m1 - mn1);
        float s0 = 0.f, s1 = 0.f;
#pragma unroll
        for (int nt = 0; nt < 8; nt++) {
            sc[nt][0] = __expf(sc[nt][0] - mn0); s0 += sc[nt][0];
            sc[nt][1] = __expf(sc[nt][1] - mn0); s0 += sc[nt][1];
            sc[nt][2] = __expf(sc[nt][2] - mn1); s1 += sc[nt][2];
            sc[nt][3] = __expf(sc[nt][3] - mn1); s1 += sc[nt][3];
        }
        s0 += __shfl_xor_sync(0xffffffffu, s0, 1);
        s0 += __shfl_xor_sync(0xffffffffu, s0, 2);
        s1 += __shfl_xor_sync(0xffffffffu, s1, 1);
        s1 += __shfl_xor_sync(0xffffffffu, s1, 2);
        l0 = l0 * a0 + s0;  m0 = mn0;
        l1 = l1 * a1 + s1;  m1 = mn1;
#pragma unroll
        for (int nt = 0; nt < 8; nt++) {
            o[nt][0] *= a0; o[nt][1] *= a0;
            o[nt][2] *= a1; o[nt][3] *= a1;
        }

        // ---- O += P @ V, 3-pass bf16 split (P frags from S regs) ----
#pragma unroll
        for (int js = 0; js < 4; js++) {
            const int n0 = 2 * js, n1 = 2 * js + 1;
            uint32_t pah[4], pal[4];
            packsplit2(sc[n0][0], sc[n0][1], pah[0], pal[0]);
            packsplit2(sc[n0][2], sc[n0][3], pah[1], pal[1]);
            packsplit2(sc[n1][0], sc[n1][1], pah[2], pal[2]);
            packsplit2(sc[n1][2], sc[n1][3], pah[3], pal[3]);
#pragma unroll
            for (int nt = 0; nt < 8; nt++) {
                const char* vp = stp + 2 * AT_TBYTES + (nt * 8 + g) * AT_PITCHB + js * 32 + 4 * t;
                uint32_t bvh[2], bvl[2];
                bvh[0] = *(const uint32_t*)vp;
                bvh[1] = *(const uint32_t*)(vp + 16);
                bvl[0] = *(const uint32_t*)(vp + AT_TBYTES);
                bvl[1] = *(const uint32_t*)(vp + AT_TBYTES + 16);
                mma_bf16(o[nt], pah, bvh);
                mma_bf16(o[nt], pal, bvh);
                mma_bf16(o[nt], pah, bvl);
            }
        }

        __syncthreads();
        if (kt + 2 < SEQ / 64) load_stage(kt & 1, kt + 2);
        else                   CP_COMMIT();
    }

    // ---- normalize and write out ----
    const float li0 = 1.f / l0, li1 = 1.f / l1;
    const int row0 = qt * 128 + mrow + g;
#pragma unroll
    for (int nt = 0; nt < 8; nt++) {
        const int col = ho + nt * 8 + 2 * t;
        float2 w0 = {o[nt][0] * li0, o[nt][1] * li0};
        float2 w1 = {o[nt][2] * li1, o[nt][3] * li1};
        *(float2*)&xout[(size_t)row0 * 2048 + col]       = w0;
        *(float2*)&xout[(size_t)(row0 + 8) * 2048 + col] = w1;
    }
}

// ---------------------------------------------------------------------------
// kernel_launch
// ---------------------------------------------------------------------------
extern "C" void kernel_launch(void* const* d_in, const int* in_sizes, int n_in,
                              void* d_out, int out_size)
{
    const float* query = (const float*)d_in[0];
    const float* key   = (const float*)d_in[1];
    const float* value = (const float*)d_in[2];
    const float* Wq    = (const float*)d_in[3];
    const float* bq    = (const float*)d_in[4];
    const float* Wk    = (const float*)d_in[5];
    const float* bk    = (const float*)d_in[6];
    const float* Wv    = (const float*)d_in[7];
    const float* bv    = (const float*)d_in[8];
    const float* Wo    = (const float*)d_in[9];
    const float* bo    = (const float*)d_in[10];
    float* out = (float*)d_out;

    float *qb, *kb, *vb, *xb;
    cudaGetSymbolAddress((void**)&qb, g_q);
    cudaGetSymbolAddress((void**)&kb, g_k);
    cudaGetSymbolAddress((void**)&vb, g_v);
    cudaGetSymbolAddress((void**)&xb, g_x);
    __nv_bfloat16 *qh, *ql, *kh, *kl, *vth, *vtl;
    cudaGetSymbolAddress((void**)&qh,  g_qh);
    cudaGetSymbolAddress((void**)&ql,  g_ql);
    cudaGetSymbolAddress((void**)&kh,  g_kh);
    cudaGetSymbolAddress((void**)&kl,  g_kl);
    cudaGetSymbolAddress((void**)&vth, g_vth);
    cudaGetSymbolAddress((void**)&vtl, g_vtl);

    cudaFuncSetAttribute(gemm_mma_kernel,
                         cudaFuncAttributeMaxDynamicSharedMemorySize, GEMM_DSMEM);
    cudaFuncSetAttribute(attn_mma_kernel,
                         cudaFuncAttributeMaxDynamicSharedMemorySize, AT_SMEM);

    dim3 gemm_grid(DIM / 128, MTOK / 128);   // (8, 32)
    const int split_blocks = NTOT / (256 * 4);   // 4096

    gemm_mma_kernel<<<gemm_grid, 256, GEMM_DSMEM>>>(query, Wq, bq, qb);
    split_bf16_kernel<<<split_blocks, 256>>>(qb, qh, ql);

    gemm_mma_kernel<<<gemm_grid, 256, GEMM_DSMEM>>>(key, Wk, bk, kb);
    split_bf16_kernel<<<split_blocks, 256>>>(kb, kh, kl);

    gemm_mma_kernel<<<gemm_grid, 256, GEMM_DSMEM>>>(value, Wv, bv, vb);
    vsplit_transpose_kernel<<<dim3(SEQ / 64, BATCH * NH), 256>>>(vb, vth, vtl);

    attn_mma_kernel<<<dim3(SEQ / 128, BATCH * NH), 256, AT_SMEM>>>(qh, ql, kh, kl, vth, vtl, xb);

    gemm_mma_kernel<<<gemm_grid, 256, GEMM_DSMEM>>>(xb, Wo, bo, out);
}

// round 6
// speedup vs baseline: 1.7140x; 1.0718x over previous
#include <cuda_runtime.h>
#include <cuda_bf16.h>
#include <cstdint>

// Problem constants
#define SEQ   2048
#define BATCH 2
#define DIM   1024
#define NH    16
#define HD    64
#define MTOK  (SEQ * BATCH)   // 4096 tokens
#define NTOT  (MTOK * DIM)    // 4M elements
#define NW    (DIM * DIM)     // 1M weight elements

// Scratch (allocation-free rule: __device__ globals)
__device__ float g_v[NTOT];                       // V projection, fp32 (pre-transpose)
// input splits
__device__ __nv_bfloat16 g_qih[NTOT], g_qil[NTOT];
__device__ __nv_bfloat16 g_kih[NTOT], g_kil[NTOT];
__device__ __nv_bfloat16 g_vih[NTOT], g_vil[NTOT];
// weight splits
__device__ __nv_bfloat16 g_wqh[NW], g_wql[NW];
__device__ __nv_bfloat16 g_wkh[NW], g_wkl[NW];
__device__ __nv_bfloat16 g_wvh[NW], g_wvl[NW];
__device__ __nv_bfloat16 g_woh[NW], g_wol[NW];
// projected Q/K splits (GEMM epilogue output)
__device__ __nv_bfloat16 g_qh[NTOT], g_ql[NTOT];
__device__ __nv_bfloat16 g_kh[NTOT], g_kl[NTOT];
// V transposed splits [bh][d][s]
__device__ __nv_bfloat16 g_vth[NTOT], g_vtl[NTOT];
// attention output splits (GEMM4 input)
__device__ __nv_bfloat16 g_xh[NTOT], g_xl[NTOT];

// ===========================================================================
// Helpers (family-safe PTX: cp.async, mma.sync, ldmatrix — no tcgen05)
// ===========================================================================
__device__ __forceinline__ uint32_t sm_u32(const void* p) {
    return (uint32_t)__cvta_generic_to_shared(p);
}
__device__ __forceinline__ void cp_async16(uint32_t smem_addr, const void* gptr) {
    asm volatile("cp.async.cg.shared.global [%0], [%1], 16;" :: "r"(smem_addr), "l"(gptr) : "memory");
}
#define CP_COMMIT() asm volatile("cp.async.commit_group;" ::: "memory")
#define CP_WAIT1()  asm volatile("cp.async.wait_group 1;" ::: "memory")

// D += A@B, m16n8k16 bf16
__device__ __forceinline__ void mma_bf16(float* c, const uint32_t* a, const uint32_t* b) {
    asm volatile(
        "mma.sync.aligned.m16n8k16.row.col.f32.bf16.bf16.f32 "
        "{%0,%1,%2,%3}, {%4,%5,%6,%7}, {%8,%9}, {%0,%1,%2,%3};"
        : "+f"(c[0]), "+f"(c[1]), "+f"(c[2]), "+f"(c[3])
        : "r"(a[0]), "r"(a[1]), "r"(a[2]), "r"(a[3]), "r"(b[0]), "r"(b[1]));
}
__device__ __forceinline__ void ldsm_x4(uint32_t* r, uint32_t addr) {
    asm volatile("ldmatrix.sync.aligned.m8n8.x4.shared.b16 {%0,%1,%2,%3}, [%4];"
                 : "=r"(r[0]), "=r"(r[1]), "=r"(r[2]), "=r"(r[3]) : "r"(addr));
}

// split-pack two floats into bf16x2 high + residual bf16x2 low
__device__ __forceinline__ void packsplit2(float x, float y, uint32_t& h, uint32_t& l) {
    __nv_bfloat162 hb = __float22bfloat162_rn(make_float2(x, y));   // .x = lo half
    h = *reinterpret_cast<uint32_t*>(&hb);
    float rx = x - __low2float(hb);
    float ry = y - __high2float(hb);
    __nv_bfloat162 lb = __float22bfloat162_rn(make_float2(rx, ry));
    l = *reinterpret_cast<uint32_t*>(&lb);
}

// ===========================================================================
// Prep: bf16 2-term split (contiguous)
// ===========================================================================
__global__ __launch_bounds__(256)
void split_bf16_kernel(const float* __restrict__ x,
                       __nv_bfloat16* __restrict__ h, __nv_bfloat16* __restrict__ l)
{
    const int i4 = (blockIdx.x * 256 + threadIdx.x) * 4;
    float4 v = *(const float4*)(x + i4);
    uint32_t h0, l0, h1, l1;
    packsplit2(v.x, v.y, h0, l0);
    packsplit2(v.z, v.w, h1, l1);
    uint2 hh = {h0, h1}, ll = {l0, l1};
    *(uint2*)(h + i4) = hh;
    *(uint2*)(l + i4) = ll;
}

// V transpose + split: v[s][b*1024+h*64+d] -> vth/vtl[(bh*64+d)*2048 + s]
__global__ __launch_bounds__(256)
void vsplit_transpose_kernel(const float* __restrict__ v,
                             __nv_bfloat16* __restrict__ vth,
                             __nv_bfloat16* __restrict__ vtl)
{
    __shared__ float ts[64][65];
    const int st = blockIdx.x;
    const int bh = blockIdx.y;
    const int bb = bh >> 4, hh = bh & 15;
    const int tid = threadIdx.x;
    {
        const int r  = tid >> 2;
        const int c0 = (tid & 3) * 16;
        const float* src = v + (size_t)(st * 64 + r) * 2048 + bb * 1024 + hh * 64 + c0;
#pragma unroll
        for (int u = 0; u < 16; u += 4) {
            float4 t = *(const float4*)(src + u);
            ts[r][c0 + u + 0] = t.x; ts[r][c0 + u + 1] = t.y;
            ts[r][c0 + u + 2] = t.z; ts[r][c0 + u + 3] = t.w;
        }
    }
    __syncthreads();
    {
        const int d  = tid >> 2;
        const int s0 = (tid & 3) * 16;
        const size_t base = (size_t)(bh * 64 + d) * 2048 + st * 64 + s0;
#pragma unroll
        for (int u = 0; u < 16; u += 2) {
            uint32_t h2, l2;
            packsplit2(ts[s0 + u][d], ts[s0 + u + 1][d], h2, l2);
            *(uint32_t*)(vth + base + u) = h2;
            *(uint32_t*)(vtl + base + u) = l2;
        }
    }
}

// ===========================================================================
// bf16 3-pass split GEMM: Y = (Xh+Xl) @ (Wh+Wl)^T + bias  (drop Xl@Wl)
// CTA 128x128, 8 warps (64x32 each), K-chunk 64, 2-stage cp.async,
// XOR-swizzled smem (128B rows), ldmatrix fragment loads.
// mode 0: Y fp32; mode 1: Y split to bf16 h/l.
// ===========================================================================
#define GK_ARR   16384                 // 128 rows x 128B per array
#define GK_STAGE (4 * GK_ARR)          // Ah, Al, Bh, Bl
#define GK_DSMEM (2 * GK_STAGE)        // 131072 bytes

__global__ __launch_bounds__(256, 1)
void gemm_bf16_kernel(const __nv_bfloat16* __restrict__ Xh, const __nv_bfloat16* __restrict__ Xl,
                      const __nv_bfloat16* __restrict__ Wh, const __nv_bfloat16* __restrict__ Wl,
                      const float* __restrict__ bias,
                      float* __restrict__ Yf,
                      __nv_bfloat16* __restrict__ Yh, __nv_bfloat16* __restrict__ Yl,
                      int mode)
{
    extern __shared__ char smem[];
    const uint32_t sb = sm_u32(smem);
    const int K = DIM, N = DIM;

    const int tid  = threadIdx.x;
    const int wid  = tid >> 5;
    const int lane = tid & 31;
    const int bm   = blockIdx.y;
    const int bn   = blockIdx.x;

    // loader: row = tid>>1, 4 chunks starting at (tid&1)*4
    const int lrow = tid >> 1;
    const int lc0  = (tid & 1) * 4;

    auto load_chunk = [&](int st, int c) {
        const uint32_t stb = sb + st * GK_STAGE + lrow * 128;
        const int k0 = c * 64;
        const __nv_bfloat16* s0 = Xh + (size_t)(bm * 128 + lrow) * K + k0;
        const __nv_bfloat16* s1 = Xl + (size_t)(bm * 128 + lrow) * K + k0;
        const __nv_bfloat16* s2 = Wh + (size_t)(bn * 128 + lrow) * K + k0;
        const __nv_bfloat16* s3 = Wl + (size_t)(bn * 128 + lrow) * K + k0;
        const int rsw = lrow & 7;
#pragma unroll
        for (int i = 0; i < 4; i++) {
            const int ch = lc0 + i;
            const uint32_t off = (uint32_t)(((ch ^ rsw) << 4));
            cp_async16(stb + 0 * GK_ARR + off, s0 + ch * 8);
            cp_async16(stb + 1 * GK_ARR + off, s1 + ch * 8);
            cp_async16(stb + 2 * GK_ARR + off, s2 + ch * 8);
            cp_async16(stb + 3 * GK_ARR + off, s3 + ch * 8);
        }
        CP_COMMIT();
    };

    load_chunk(0, 0);
    load_chunk(1, 1);

    const int wm = (wid & 1) * 64;
    const int wn = (wid >> 1) * 32;
    const int g  = lane >> 2;
    const int t  = lane & 3;
    const int sw = lane & 7;
    // ldmatrix lane geometry
    const int a_row = (lane & 7) + ((lane >> 3) & 1) * 8;   // A: m0/m1 rows, m2/m3 k-hi
    const int a_chi = lane >> 4;
    const int b_row = (lane & 7) + ((lane >> 4) & 1) * 8;   // B: m0/m1 = ntE lo/hi
    const int b_chi = (lane >> 3) & 1;

    float acc[4][4][4];
#pragma unroll
    for (int mt = 0; mt < 4; mt++)
#pragma unroll
        for (int nt = 0; nt < 4; nt++)
#pragma unroll
            for (int e = 0; e < 4; e++) acc[mt][nt][e] = 0.f;

    for (int c = 0; c < 16; c++) {
        CP_WAIT1();
        __syncthreads();
        const uint32_t stb = sb + (c & 1) * GK_STAGE;

#pragma unroll
        for (int ks = 0; ks < 4; ks++) {
            uint32_t Ah[4][4], Al[4][4], Bh[2][4], Bl[2][4];
#pragma unroll
            for (int mt = 0; mt < 4; mt++) {
                const uint32_t ro = (uint32_t)((wm + mt * 16 + a_row) * 128
                                  + (((ks * 2 + a_chi) ^ sw) << 4));
                ldsm_x4(Ah[mt], stb + 0 * GK_ARR + ro);
                ldsm_x4(Al[mt], stb + 1 * GK_ARR + ro);
            }
#pragma unroll
            for (int p = 0; p < 2; p++) {
                const uint32_t ro = (uint32_t)((wn + p * 16 + b_row) * 128
                                  + (((ks * 2 + b_chi) ^ sw) << 4));
                ldsm_x4(Bh[p], stb + 2 * GK_ARR + ro);
                ldsm_x4(Bl[p], stb + 3 * GK_ARR + ro);
            }
#pragma unroll
            for (int mt = 0; mt < 4; mt++)
#pragma unroll
                for (int nt = 0; nt < 4; nt++) {
                    const int p = nt >> 1, s2 = (nt & 1) * 2;
                    uint32_t bh[2] = {Bh[p][s2], Bh[p][s2 + 1]};
                    uint32_t bl[2] = {Bl[p][s2], Bl[p][s2 + 1]};
                    mma_bf16(acc[mt][nt], Ah[mt], bh);
                    mma_bf16(acc[mt][nt], Al[mt], bh);
                    mma_bf16(acc[mt][nt], Ah[mt], bl);
                }
        }

        __syncthreads();
        if (c + 2 < 16) load_chunk(c & 1, c + 2);
        else            CP_COMMIT();
    }

    // epilogue
#pragma unroll
    for (int mt = 0; mt < 4; mt++) {
        const int row = bm * 128 + wm + mt * 16 + g;
#pragma unroll
        for (int nt = 0; nt < 4; nt++) {
            const int col = bn * 128 + wn + nt * 8 + 2 * t;
            float2 bi = *(const float2*)&bias[col];
            const float c0 = acc[mt][nt][0] + bi.x;
            const float c1 = acc[mt][nt][1] + bi.y;
            const float c2 = acc[mt][nt][2] + bi.x;
            const float c3 = acc[mt][nt][3] + bi.y;
            if (mode == 0) {
                float2 r01 = {c0, c1}, r23 = {c2, c3};
                *(float2*)&Yf[(size_t)row * N + col]       = r01;
                *(float2*)&Yf[(size_t)(row + 8) * N + col] = r23;
            } else {
                uint32_t h0, l0, h1, l1;
                packsplit2(c0, c1, h0, l0);
                packsplit2(c2, c3, h1, l1);
                *(uint32_t*)&Yh[(size_t)row * N + col]       = h0;
                *(uint32_t*)&Yl[(size_t)row * N + col]       = l0;
                *(uint32_t*)&Yh[(size_t)(row + 8) * N + col] = h1;
                *(uint32_t*)&Yl[(size_t)(row + 8) * N + col] = l1;
            }
        }
    }
}

// ===========================================================================
// Flash attention (bf16 3-pass split MMAs, fp32 accum) — round-5 design,
// epilogue now writes bf16 split directly (feeds O-projection GEMM).
// ===========================================================================
#define AT_PITCHB 144
#define AT_QBYTES (128 * AT_PITCHB)
#define AT_TBYTES (64 * AT_PITCHB)
#define AT_ST0    (2 * AT_QBYTES)
#define AT_STSZ   (4 * AT_TBYTES)
#define AT_SMEM   (AT_ST0 + 2 * AT_STSZ)  // 110592 bytes

__global__ __launch_bounds__(256, 2)
void attn_mma_kernel(const __nv_bfloat16* __restrict__ qh, const __nv_bfloat16* __restrict__ ql,
                     const __nv_bfloat16* __restrict__ kh, const __nv_bfloat16* __restrict__ kl,
                     const __nv_bfloat16* __restrict__ vth, const __nv_bfloat16* __restrict__ vtl,
                     __nv_bfloat16* __restrict__ xh, __nv_bfloat16* __restrict__ xl)
{
    extern __shared__ char smem[];
    const uint32_t sbase = sm_u32(smem);

    const int tid  = threadIdx.x;
    const int wid  = tid >> 5;
    const int lane = tid & 31;
    const int g    = lane >> 2;
    const int t    = lane & 3;
    const int qt   = blockIdx.x;
    const int bh   = blockIdx.y;
    const int bb   = bh >> 4, hh = bh & 15;
    const int ho   = bb * 1024 + hh * 64;

    // ---- load Q tiles ----
    {
        const int r  = tid >> 1;
        const int c0 = (tid & 1) * 4;
        const __nv_bfloat16* sh = qh + (size_t)(qt * 128 + r) * 2048 + ho + c0 * 8;
        const __nv_bfloat16* sl = ql + (size_t)(qt * 128 + r) * 2048 + ho + c0 * 8;
        const uint32_t dh = sbase + r * AT_PITCHB + c0 * 16;
        const uint32_t dl = dh + AT_QBYTES;
#pragma unroll
        for (int i = 0; i < 4; i++) {
            cp_async16(dh + i * 16, sh + i * 8);
            cp_async16(dl + i * 16, sl + i * 8);
        }
        CP_COMMIT();
    }

    auto load_stage = [&](int s, int kt) {
        const uint32_t stb = sbase + AT_ST0 + s * AT_STSZ;
        const int r     = tid & 63;
        const int which = tid >> 6;
        const __nv_bfloat16* src;
        if (which == 0)      src = kh  + (size_t)(kt * 64 + r) * 2048 + ho;
        else if (which == 1) src = kl  + (size_t)(kt * 64 + r) * 2048 + ho;
        else if (which == 2) src = vth + (size_t)(bh * 64 + r) * 2048 + kt * 64;
        else                 src = vtl + (size_t)(bh * 64 + r) * 2048 + kt * 64;
        const uint32_t dst = stb + which * AT_TBYTES + r * AT_PITCHB;
#pragma unroll
        for (int i = 0; i < 8; i++) cp_async16(dst + i * 16, src + i * 8);
        CP_COMMIT();
    };

    load_stage(0, 0);
    load_stage(1, 1);

    float m0 = -1e30f, m1 = -1e30f, l0 = 0.f, l1 = 0.f;
    float o[8][4];
#pragma unroll
    for (int nt = 0; nt < 8; nt++)
#pragma unroll
        for (int e = 0; e < 4; e++) o[nt][e] = 0.f;

    const int mrow = wid * 16;
    const char* Qh0 = smem + (mrow + g) * AT_PITCHB + 4 * t;
    const char* Ql0 = Qh0 + AT_QBYTES;

    for (int kt = 0; kt < SEQ / 64; kt++) {
        CP_WAIT1();
        __syncthreads();
        const char* stp = smem + AT_ST0 + (kt & 1) * AT_STSZ;

        float sc[8][4];
#pragma unroll
        for (int nt = 0; nt < 8; nt++)
#pragma unroll
            for (int e = 0; e < 4; e++) sc[nt][e] = 0.f;

#pragma unroll
        for (int ks = 0; ks < 4; ks++) {
            const int ko = ks * 32;
            uint32_t ah[4], al[4];
            ah[0] = *(const uint32_t*)(Qh0 + ko);
            ah[1] = *(const uint32_t*)(Qh0 + 8 * AT_PITCHB + ko);
            ah[2] = *(const uint32_t*)(Qh0 + ko + 16);
            ah[3] = *(const uint32_t*)(Qh0 + 8 * AT_PITCHB + ko + 16);
            al[0] = *(const uint32_t*)(Ql0 + ko);
            al[1] = *(const uint32_t*)(Ql0 + 8 * AT_PITCHB + ko);
            al[2] = *(const uint32_t*)(Ql0 + ko + 16);
            al[3] = *(const uint32_t*)(Ql0 + 8 * AT_PITCHB + ko + 16);
#pragma unroll
            for (int nt = 0; nt < 8; nt++) {
                const char* kp = stp + (nt * 8 + g) * AT_PITCHB + ko + 4 * t;
                uint32_t bhf[2], blf[2];
                bhf[0] = *(const uint32_t*)kp;
                bhf[1] = *(const uint32_t*)(kp + 16);
                blf[0] = *(const uint32_t*)(kp + AT_TBYTES);
                blf[1] = *(const uint32_t*)(kp + AT_TBYTES + 16);
                mma_bf16(sc[nt], ah, bhf);
                mma_bf16(sc[nt], al, bhf);
                mma_bf16(sc[nt], ah, blf);
            }
        }

        float mx0 = -1e30f, mx1 = -1e30f;
#pragma unroll
        for (int nt = 0; nt < 8; nt++) {
            mx0 = fmaxf(mx0, fmaxf(sc[nt][0], sc[nt][1]));
            mx1 = fmaxf(mx1, fmaxf(sc[nt][2], sc[nt][3]));
        }
        mx0 = fmaxf(mx0, __shfl_xor_sync(0xffffffffu, mx0, 1));
        mx0 = fmaxf(mx0, __shfl_xor_sync(0xffffffffu, mx0, 2));
        mx1 = fmaxf(mx1, __shfl_xor_sync(0xffffffffu, mx1, 1));
        mx1 = fmaxf(mx1, __shfl_xor_sync(0xffffffffu, mx1, 2));
        const float mn0 = fmaxf(m0, mx0), mn1 = fmaxf(m1, mx1);
        const float a0 = __expf(m0 - mn0), a1 = __expf(m1 - mn1);
        float s0 = 0.f, s1 = 0.f;
#pragma unroll
        for (int nt = 0; nt < 8; nt++) {
            sc[nt][0] = __expf(sc[nt][0] - mn0); s0 += sc[nt][0];
            sc[nt][1] = __expf(sc[nt][1] - mn0); s0 += sc[nt][1];
            sc[nt][2] = __expf(sc[nt][2] - mn1); s1 += sc[nt][2];
            sc[nt][3] = __expf(sc[nt][3] - mn1); s1 += sc[nt][3];
        }
        s0 += __shfl_xor_sync(0xffffffffu, s0, 1);
        s0 += __shfl_xor_sync(0xffffffffu, s0, 2);
        s1 += __shfl_xor_sync(0xffffffffu, s1, 1);
        s1 += __shfl_xor_sync(0xffffffffu, s1, 2);
        l0 = l0 * a0 + s0;  m0 = mn0;
        l1 = l1 * a1 + s1;  m1 = mn1;
#pragma unroll
        for (int nt = 0; nt < 8; nt++) {
            o[nt][0] *= a0; o[nt][1] *= a0;
            o[nt][2] *= a1; o[nt][3] *= a1;
        }

#pragma unroll
        for (int js = 0; js < 4; js++) {
            const int n0 = 2 * js, n1 = 2 * js + 1;
            uint32_t pah[4], pal[4];
            packsplit2(sc[n0][0], sc[n0][1], pah[0], pal[0]);
            packsplit2(sc[n0][2], sc[n0][3], pah[1], pal[1]);
            packsplit2(sc[n1][0], sc[n1][1], pah[2], pal[2]);
            packsplit2(sc[n1][2], sc[n1][3], pah[3], pal[3]);
#pragma unroll
            for (int nt = 0; nt < 8; nt++) {
                const char* vp = stp + 2 * AT_TBYTES + (nt * 8 + g) * AT_PITCHB + js * 32 + 4 * t;
                uint32_t bvh[2], bvl[2];
                bvh[0] = *(const uint32_t*)vp;
                bvh[1] = *(const uint32_t*)(vp + 16);
                bvl[0] = *(const uint32_t*)(vp + AT_TBYTES);
                bvl[1] = *(const uint32_t*)(vp + AT_TBYTES + 16);
                mma_bf16(o[nt], pah, bvh);
                mma_bf16(o[nt], pal, bvh);
                mma_bf16(o[nt], pah, bvl);
            }
        }

        __syncthreads();
        if (kt + 2 < SEQ / 64) load_stage(kt & 1, kt + 2);
        else                   CP_COMMIT();
    }

    // ---- normalize, split to bf16 h/l, write out ----
    const float li0 = 1.f / l0, li1 = 1.f / l1;
    const int row0 = qt * 128 + mrow + g;
#pragma unroll
    for (int nt = 0; nt < 8; nt++) {
        const int col = ho + nt * 8 + 2 * t;
        uint32_t h0, lo0, h1, lo1;
        packsplit2(o[nt][0] * li0, o[nt][1] * li0, h0, lo0);
        packsplit2(o[nt][2] * li1, o[nt][3] * li1, h1, lo1);
        *(uint32_t*)&xh[(size_t)row0 * 2048 + col]       = h0;
        *(uint32_t*)&xl[(size_t)row0 * 2048 + col]       = lo0;
        *(uint32_t*)&xh[(size_t)(row0 + 8) * 2048 + col] = h1;
        *(uint32_t*)&xl[(size_t)(row0 + 8) * 2048 + col] = lo1;
    }
}

// ---------------------------------------------------------------------------
// kernel_launch
// ---------------------------------------------------------------------------
extern "C" void kernel_launch(void* const* d_in, const int* in_sizes, int n_in,
                              void* d_out, int out_size)
{
    const float* query = (const float*)d_in[0];
    const float* key   = (const float*)d_in[1];
    const float* value = (const float*)d_in[2];
    const float* Wq    = (const float*)d_in[3];
    const float* bq    = (const float*)d_in[4];
    const float* Wk    = (const float*)d_in[5];
    const float* bk    = (const float*)d_in[6];
    const float* Wv    = (const float*)d_in[7];
    const float* bv    = (const float*)d_in[8];
    const float* Wo    = (const float*)d_in[9];
    const float* bo    = (const float*)d_in[10];
    float* out = (float*)d_out;

    float* vb;
    cudaGetSymbolAddress((void**)&vb, g_v);
    __nv_bfloat16 *qih,*qil,*kih,*kil,*vih,*vil;
    __nv_bfloat16 *wqh,*wql,*wkh,*wkl,*wvh,*wvl,*woh,*wol;
    __nv_bfloat16 *qh,*ql,*kh,*kl,*vth,*vtl,*xh,*xl;
    cudaGetSymbolAddress((void**)&qih, g_qih); cudaGetSymbolAddress((void**)&qil, g_qil);
    cudaGetSymbolAddress((void**)&kih, g_kih); cudaGetSymbolAddress((void**)&kil, g_kil);
    cudaGetSymbolAddress((void**)&vih, g_vih); cudaGetSymbolAddress((void**)&vil, g_vil);
    cudaGetSymbolAddress((void**)&wqh, g_wqh); cudaGetSymbolAddress((void**)&wql, g_wql);
    cudaGetSymbolAddress((void**)&wkh, g_wkh); cudaGetSymbolAddress((void**)&wkl, g_wkl);
    cudaGetSymbolAddress((void**)&wvh, g_wvh); cudaGetSymbolAddress((void**)&wvl, g_wvl);
    cudaGetSymbolAddress((void**)&woh, g_woh); cudaGetSymbolAddress((void**)&wol, g_wol);
    cudaGetSymbolAddress((void**)&qh,  g_qh);  cudaGetSymbolAddress((void**)&ql,  g_ql);
    cudaGetSymbolAddress((void**)&kh,  g_kh);  cudaGetSymbolAddress((void**)&kl,  g_kl);
    cudaGetSymbolAddress((void**)&vth, g_vth); cudaGetSymbolAddress((void**)&vtl, g_vtl);
    cudaGetSymbolAddress((void**)&xh,  g_xh);  cudaGetSymbolAddress((void**)&xl,  g_xl);

    cudaFuncSetAttribute(gemm_bf16_kernel,
                         cudaFuncAttributeMaxDynamicSharedMemorySize, GK_DSMEM);
    cudaFuncSetAttribute(attn_mma_kernel,
                         cudaFuncAttributeMaxDynamicSharedMemorySize, AT_SMEM);

    dim3 gemm_grid(DIM / 128, MTOK / 128);   // (8, 32)
    const int xblocks = NTOT / 1024;         // 4096
    const int wblocks = NW / 1024;           // 1024

    // input + weight splits
    split_bf16_kernel<<<xblocks, 256>>>(query, qih, qil);
    split_bf16_kernel<<<xblocks, 256>>>(key,   kih, kil);
    split_bf16_kernel<<<xblocks, 256>>>(value, vih, vil);
    split_bf16_kernel<<<wblocks, 256>>>(Wq, wqh, wql);
    split_bf16_kernel<<<wblocks, 256>>>(Wk, wkh, wkl);
    split_bf16_kernel<<<wblocks, 256>>>(Wv, wvh, wvl);
    split_bf16_kernel<<<wblocks, 256>>>(Wo, woh, wol);

    // projections (Q,K: split-epilogue; V: fp32 for transpose)
    gemm_bf16_kernel<<<gemm_grid, 256, GK_DSMEM>>>(qih, qil, wqh, wql, bq, nullptr, qh, ql, 1);
    gemm_bf16_kernel<<<gemm_grid, 256, GK_DSMEM>>>(kih, kil, wkh, wkl, bk, nullptr, kh, kl, 1);
    gemm_bf16_kernel<<<gemm_grid, 256, GK_DSMEM>>>(vih, vil, wvh, wvl, bv, vb, nullptr, nullptr, 0);
    vsplit_transpose_kernel<<<dim3(SEQ / 64, BATCH * NH), 256>>>(vb, vth, vtl);

    // attention (writes split x)
    attn_mma_kernel<<<dim3(SEQ / 128, BATCH * NH), 256, AT_SMEM>>>(qh, ql, kh, kl, vth, vtl, xh, xl);

    // output projection
    gemm_bf16_kernel<<<gemm_grid, 256, GK_DSMEM>>>(xh, xl, woh, wol, bo, out, nullptr, nullptr, 0);
}

// round 7
// speedup vs baseline: 2.0823x; 1.2148x over previous
#include <cuda_runtime.h>
#include <cuda_bf16.h>
#include <cuda_fp16.h>
#include <cstdint>

// Problem constants
#define SEQ   2048
#define BATCH 2
#define DIM   1024
#define NH    16
#define HD    64
#define MTOK  (SEQ * BATCH)   // 4096 tokens
#define NTOT  (MTOK * DIM)    // 4M elements
#define NW    (DIM * DIM)     // 1M weight elements

// Scratch (allocation-free rule: __device__ globals)
__device__ float g_v[NTOT];                       // V projection, fp32 (pre-transpose)
__device__ __nv_bfloat16 g_qih[NTOT], g_qil[NTOT];
__device__ __nv_bfloat16 g_kih[NTOT], g_kil[NTOT];
__device__ __nv_bfloat16 g_vih[NTOT], g_vil[NTOT];
__device__ __nv_bfloat16 g_wqh[NW], g_wql[NW];
__device__ __nv_bfloat16 g_wkh[NW], g_wkl[NW];
__device__ __nv_bfloat16 g_wvh[NW], g_wvl[NW];
__device__ __nv_bfloat16 g_woh[NW], g_wol[NW];
__device__ __nv_bfloat16 g_qh[NTOT], g_ql[NTOT];
__device__ __nv_bfloat16 g_kh[NTOT], g_kl[NTOT];
__device__ __half        g_vt[NTOT];              // V transposed [bh][d][s], fp16 single
__device__ __nv_bfloat16 g_xh[NTOT], g_xl[NTOT];

// ===========================================================================
// Helpers (family-safe PTX: cp.async, mma.sync, ldmatrix — no tcgen05)
// ===========================================================================
__device__ __forceinline__ uint32_t sm_u32(const void* p) {
    return (uint32_t)__cvta_generic_to_shared(p);
}
__device__ __forceinline__ void cp_async16(uint32_t smem_addr, const void* gptr) {
    asm volatile("cp.async.cg.shared.global [%0], [%1], 16;" :: "r"(smem_addr), "l"(gptr) : "memory");
}
#define CP_COMMIT() asm volatile("cp.async.commit_group;" ::: "memory")
#define CP_WAIT1()  asm volatile("cp.async.wait_group 1;" ::: "memory")
#define CP_WAIT2()  asm volatile("cp.async.wait_group 2;" ::: "memory")

__device__ __forceinline__ void mma_bf16(float* c, const uint32_t* a, const uint32_t* b) {
    asm volatile(
        "mma.sync.aligned.m16n8k16.row.col.f32.bf16.bf16.f32 "
        "{%0,%1,%2,%3}, {%4,%5,%6,%7}, {%8,%9}, {%0,%1,%2,%3};"
        : "+f"(c[0]), "+f"(c[1]), "+f"(c[2]), "+f"(c[3])
        : "r"(a[0]), "r"(a[1]), "r"(a[2]), "r"(a[3]), "r"(b[0]), "r"(b[1]));
}
__device__ __forceinline__ void mma_f16(float* c, const uint32_t* a, const uint32_t* b) {
    asm volatile(
        "mma.sync.aligned.m16n8k16.row.col.f32.f16.f16.f32 "
        "{%0,%1,%2,%3}, {%4,%5,%6,%7}, {%8,%9}, {%0,%1,%2,%3};"
        : "+f"(c[0]), "+f"(c[1]), "+f"(c[2]), "+f"(c[3])
        : "r"(a[0]), "r"(a[1]), "r"(a[2]), "r"(a[3]), "r"(b[0]), "r"(b[1]));
}
__device__ __forceinline__ void ldsm_x4(uint32_t* r, uint32_t addr) {
    asm volatile("ldmatrix.sync.aligned.m8n8.x4.shared.b16 {%0,%1,%2,%3}, [%4];"
                 : "=r"(r[0]), "=r"(r[1]), "=r"(r[2]), "=r"(r[3]) : "r"(addr));
}

// split-pack two floats into bf16x2 high + residual bf16x2 low
__device__ __forceinline__ void packsplit2(float x, float y, uint32_t& h, uint32_t& l) {
    __nv_bfloat162 hb = __float22bfloat162_rn(make_float2(x, y));
    h = *reinterpret_cast<uint32_t*>(&hb);
    float rx = x - __low2float(hb);
    float ry = y - __high2float(hb);
    __nv_bfloat162 lb = __float22bfloat162_rn(make_float2(rx, ry));
    l = *reinterpret_cast<uint32_t*>(&lb);
}
__device__ __forceinline__ uint32_t packh2(float x, float y) {
    __half2 hp = __float22half2_rn(make_float2(x, y));
    return *reinterpret_cast<uint32_t*>(&hp);
}

// ===========================================================================
// Prep: merged bf16 2-term splits
// ===========================================================================
__device__ __forceinline__ void split_body(const float* __restrict__ x,
                                           __nv_bfloat16* __restrict__ h,
                                           __nv_bfloat16* __restrict__ l)
{
    const int i4 = (blockIdx.x * 256 + threadIdx.x) * 4;
    float4 v = *(const float4*)(x + i4);
    uint32_t h0, l0, h1, l1;
    packsplit2(v.x, v.y, h0, l0);
    packsplit2(v.z, v.w, h1, l1);
    uint2 hh = {h0, h1}, ll = {l0, l1};
    *(uint2*)(h + i4) = hh;
    *(uint2*)(l + i4) = ll;
}

__global__ __launch_bounds__(256)
void split_inputs_kernel(const float* __restrict__ q, const float* __restrict__ k,
                         const float* __restrict__ v)
{
    const int y = blockIdx.y;
    const float* src = (y == 0) ? q : (y == 1) ? k : v;
    __nv_bfloat16* h = (y == 0) ? g_qih : (y == 1) ? g_kih : g_vih;
    __nv_bfloat16* l = (y == 0) ? g_qil : (y == 1) ? g_kil : g_vil;
    split_body(src, h, l);
}

__global__ __launch_bounds__(256)
void split_weights_kernel(const float* __restrict__ wq, const float* __restrict__ wk,
                          const float* __restrict__ wv, const float* __restrict__ wo)
{
    const int y = blockIdx.y;
    const float* src = (y == 0) ? wq : (y == 1) ? wk : (y == 2) ? wv : wo;
    __nv_bfloat16* h = (y == 0) ? g_wqh : (y == 1) ? g_wkh : (y == 2) ? g_wvh : g_woh;
    __nv_bfloat16* l = (y == 0) ? g_wql : (y == 1) ? g_wkl : (y == 2) ? g_wvl : g_wol;
    split_body(src, h, l);
}

// V transpose + fp16: g_v[s][b*1024+h*64+d] -> g_vt[(bh*64+d)*2048 + s]
__global__ __launch_bounds__(256)
void vsplit_transpose_kernel()
{
    __shared__ float ts[64][65];
    const int st = blockIdx.x;
    const int bh = blockIdx.y;
    const int bb = bh >> 4, hh = bh & 15;
    const int tid = threadIdx.x;
    {
        const int r  = tid >> 2;
        const int c0 = (tid & 3) * 16;
        const float* src = g_v + (size_t)(st * 64 + r) * 2048 + bb * 1024 + hh * 64 + c0;
#pragma unroll
        for (int u = 0; u < 16; u += 4) {
            float4 t = *(const float4*)(src + u);
            ts[r][c0 + u + 0] = t.x; ts[r][c0 + u + 1] = t.y;
            ts[r][c0 + u + 2] = t.z; ts[r][c0 + u + 3] = t.w;
        }
    }
    __syncthreads();
    {
        const int d  = tid >> 2;
        const int s0 = (tid & 3) * 16;
        const size_t base = (size_t)(bh * 64 + d) * 2048 + st * 64 + s0;
#pragma unroll
        for (int u = 0; u < 16; u += 2)
            *(uint32_t*)(g_vt + base + u) = packh2(ts[s0 + u][d], ts[s0 + u + 1][d]);
    }
}

// ===========================================================================
// bf16 3-pass split GEMM core: Y = (Xh+Xl)@(Wh+Wl)^T + bias (drop Xl@Wl)
// CTA 128x128, 8 warps (64x32), K-chunk 32, 2-stage cp.async,
// pitch-80 smem rows (conflict-free ldsm, no swizzle).
// ===========================================================================
#define GK_PITCH 80
#define GK_ARR   (128 * GK_PITCH)      // 10240
#define GK_STAGE (4 * GK_ARR)          // 40960: Ah, Al, Bh, Bl
#define GK_DSMEM (2 * GK_STAGE)        // 81920 bytes -> 2 CTAs/SM

__device__ __forceinline__ void gemm_core(
    const __nv_bfloat16* __restrict__ Xh, const __nv_bfloat16* __restrict__ Xl,
    const __nv_bfloat16* __restrict__ Wh, const __nv_bfloat16* __restrict__ Wl,
    const float* __restrict__ bias,
    float* __restrict__ Yf, __nv_bfloat16* __restrict__ Yh, __nv_bfloat16* __restrict__ Yl,
    int mode, char* smem)
{
    const uint32_t sb = sm_u32(smem);
    const int K = DIM, N = DIM;

    const int tid  = threadIdx.x;
    const int wid  = tid >> 5;
    const int lane = tid & 31;
    const int bm   = blockIdx.y;
    const int bn   = blockIdx.x;

    const int lrow = tid >> 1;          // 0..127
    const int lc0  = (tid & 1) * 2;     // 2 chunks of 16B each

    auto load_chunk = [&](int st, int c) {
        const uint32_t stb = sb + st * GK_STAGE + lrow * GK_PITCH;
        const int k0 = c * 32;
        const __nv_bfloat16* s0 = Xh + (size_t)(bm * 128 + lrow) * K + k0;
        const __nv_bfloat16* s1 = Xl + (size_t)(bm * 128 + lrow) * K + k0;
        const __nv_bfloat16* s2 = Wh + (size_t)(bn * 128 + lrow) * K + k0;
        const __nv_bfloat16* s3 = Wl + (size_t)(bn * 128 + lrow) * K + k0;
#pragma unroll
        for (int i = 0; i < 2; i++) {
            const int ch = lc0 + i;
            const uint32_t off = (uint32_t)(ch << 4);
            cp_async16(stb + 0 * GK_ARR + off, s0 + ch * 8);
            cp_async16(stb + 1 * GK_ARR + off, s1 + ch * 8);
            cp_async16(stb + 2 * GK_ARR + off, s2 + ch * 8);
            cp_async16(stb + 3 * GK_ARR + off, s3 + ch * 8);
        }
        CP_COMMIT();
    };

    load_chunk(0, 0);
    load_chunk(1, 1);

    const int wm = (wid & 1) * 64;
    const int wn = (wid >> 1) * 32;
    const int g  = lane >> 2;
    const int t  = lane & 3;
    const int a_row = (lane & 7) + ((lane >> 3) & 1) * 8;
    const int a_chi = lane >> 4;
    const int b_row = (lane & 7) + ((lane >> 4) & 1) * 8;
    const int b_chi = (lane >> 3) & 1;

    float acc[4][4][4];
#pragma unroll
    for (int mt = 0; mt < 4; mt++)
#pragma unroll
        for (int nt = 0; nt < 4; nt++)
#pragma unroll
            for (int e = 0; e < 4; e++) acc[mt][nt][e] = 0.f;

    for (int c = 0; c < 32; c++) {
        CP_WAIT1();
        __syncthreads();
        const uint32_t stb = sb + (c & 1) * GK_STAGE;

#pragma unroll
        for (int ks = 0; ks < 2; ks++) {
            uint32_t Ah[4][4], Al[4][4], Bh[2][4], Bl[2][4];
#pragma unroll
            for (int mt = 0; mt < 4; mt++) {
                const uint32_t ro = (uint32_t)((wm + mt * 16 + a_row) * GK_PITCH
                                  + ((ks * 2 + a_chi) << 4));
                ldsm_x4(Ah[mt], stb + 0 * GK_ARR + ro);
                ldsm_x4(Al[mt], stb + 1 * GK_ARR + ro);
            }
#pragma unroll
            for (int p = 0; p < 2; p++) {
                const uint32_t ro = (uint32_t)((wn + p * 16 + b_row) * GK_PITCH
                                  + ((ks * 2 + b_chi) << 4));
                ldsm_x4(Bh[p], stb + 2 * GK_ARR + ro);
                ldsm_x4(Bl[p], stb + 3 * GK_ARR + ro);
            }
#pragma unroll
            for (int mt = 0; mt < 4; mt++)
#pragma unroll
                for (int nt = 0; nt < 4; nt++) {
                    const int p = nt >> 1, s2 = (nt & 1) * 2;
                    uint32_t bh[2] = {Bh[p][s2], Bh[p][s2 + 1]};
                    uint32_t bl[2] = {Bl[p][s2], Bl[p][s2 + 1]};
                    mma_bf16(acc[mt][nt], Ah[mt], bh);
                    mma_bf16(acc[mt][nt], Al[mt], bh);
                    mma_bf16(acc[mt][nt], Ah[mt], bl);
                }
        }

        __syncthreads();
        if (c + 2 < 32) load_chunk(c & 1, c + 2);
        else            CP_COMMIT();
    }

#pragma unroll
    for (int mt = 0; mt < 4; mt++) {
        const int row = bm * 128 + wm + mt * 16 + g;
#pragma unroll
        for (int nt = 0; nt < 4; nt++) {
            const int col = bn * 128 + wn + nt * 8 + 2 * t;
            float2 bi = *(const float2*)&bias[col];
            const float c0 = acc[mt][nt][0] + bi.x;
            const float c1 = acc[mt][nt][1] + bi.y;
            const float c2 = acc[mt][nt][2] + bi.x;
            const float c3 = acc[mt][nt][3] + bi.y;
            if (mode == 0) {
                float2 r01 = {c0, c1}, r23 = {c2, c3};
                *(float2*)&Yf[(size_t)row * N + col]       = r01;
                *(float2*)&Yf[(size_t)(row + 8) * N + col] = r23;
            } else {
                uint32_t h0, l0, h1, l1;
                packsplit2(c0, c1, h0, l0);
                packsplit2(c2, c3, h1, l1);
                *(uint32_t*)&Yh[(size_t)row * N + col]       = h0;
                *(uint32_t*)&Yl[(size_t)row * N + col]       = l0;
                *(uint32_t*)&Yh[(size_t)(row + 8) * N + col] = h1;
                *(uint32_t*)&Yl[(size_t)(row + 8) * N + col] = l1;
            }
        }
    }
}

__global__ __launch_bounds__(256, 2)
void gemm_qkv_kernel(const float* __restrict__ bq, const float* __restrict__ bk,
                     const float* __restrict__ bv)
{
    extern __shared__ char smem[];
    const int z = blockIdx.z;
    if (z == 0)      gemm_core(g_qih, g_qil, g_wqh, g_wql, bq, nullptr, g_qh, g_ql, 1, smem);
    else if (z == 1) gemm_core(g_kih, g_kil, g_wkh, g_wkl, bk, nullptr, g_kh, g_kl, 1, smem);
    else             gemm_core(g_vih, g_vil, g_wvh, g_wvl, bv, g_v, nullptr, nullptr, 0, smem);
}

__global__ __launch_bounds__(256, 2)
void gemm_o_kernel(const float* __restrict__ bo, float* __restrict__ out)
{
    extern __shared__ char smem[];
    gemm_core(g_xh, g_xl, g_woh, g_wol, bo, out, nullptr, nullptr, 0, smem);
}

// ===========================================================================
// Flash attention: QK^T bf16 3-pass, PV single-pass fp16. fp32 accum.
// CTA = 128 q-rows x one (b,h); 8 warps x 16 rows; 64-key tiles;
// double-buffered K/V cp.async; Q fragments hoisted to registers.
// ===========================================================================
#define AT_PITCHB 144
#define AT_QBYTES (128 * AT_PITCHB)        // 18432 per Q array
#define AT_KARR   (64 * AT_PITCHB)         // 9216
#define AT_ST0    (2 * AT_QBYTES)          // 36864
#define AT_STSZ   (3 * AT_KARR)            // 27648: KH, KL, VT
#define AT_SMEM   (AT_ST0 + 2 * AT_STSZ)   // 92160 bytes -> 2 CTAs/SM

__global__ __launch_bounds__(256, 2)
void attn_mma_kernel()
{
    extern __shared__ char smem[];
    const uint32_t sbase = sm_u32(smem);

    const int tid  = threadIdx.x;
    const int wid  = tid >> 5;
    const int lane = tid & 31;
    const int g    = lane >> 2;
    const int t    = lane & 3;
    const int qt   = blockIdx.x;
    const int bh   = blockIdx.y;
    const int bb   = bh >> 4, hh = bh & 15;
    const int ho   = bb * 1024 + hh * 64;

    // ---- Q tile load (group 1) ----
    {
        const int r  = tid >> 1;
        const int c0 = (tid & 1) * 4;
        const __nv_bfloat16* sh = g_qh + (size_t)(qt * 128 + r) * 2048 + ho + c0 * 8;
        const __nv_bfloat16* sl = g_ql + (size_t)(qt * 128 + r) * 2048 + ho + c0 * 8;
        const uint32_t dh = sbase + r * AT_PITCHB + c0 * 16;
        const uint32_t dl = dh + AT_QBYTES;
#pragma unroll
        for (int i = 0; i < 4; i++) {
            cp_async16(dh + i * 16, sh + i * 8);
            cp_async16(dl + i * 16, sl + i * 8);
        }
        CP_COMMIT();
    }

    auto load_stage = [&](int s, int kt) {
        const uint32_t stb = sbase + AT_ST0 + s * AT_STSZ;
        const int which = tid >> 6;
        const int r = tid & 63;
        if (which < 2) {
            const __nv_bfloat16* src = (which == 0 ? g_kh : g_kl)
                                     + (size_t)(kt * 64 + r) * 2048 + ho;
            const uint32_t dst = stb + which * AT_KARR + r * AT_PITCHB;
#pragma unroll
            for (int i = 0; i < 8; i++) cp_async16(dst + i * 16, src + i * 8);
        } else {
            const int half = which - 2;
            const __half* src = g_vt + (size_t)(bh * 64 + r) * 2048 + kt * 64 + half * 32;
            const uint32_t dst = stb + 2 * AT_KARR + r * AT_PITCHB + half * 64;
#pragma unroll
            for (int i = 0; i < 4; i++) cp_async16(dst + i * 16, src + i * 8);
        }
        CP_COMMIT();
    };

    load_stage(0, 0);
    load_stage(1, 1);

    // Q group done -> hoist Q fragments to registers
    CP_WAIT2();
    __syncthreads();
    uint32_t qah[4][4], qal[4][4];
    {
        const char* Qh0 = smem + (wid * 16 + g) * AT_PITCHB + 4 * t;
        const char* Ql0 = Qh0 + AT_QBYTES;
#pragma unroll
        for (int ks = 0; ks < 4; ks++) {
            const int ko = ks * 32;
            qah[ks][0] = *(const uint32_t*)(Qh0 + ko);
            qah[ks][1] = *(const uint32_t*)(Qh0 + 8 * AT_PITCHB + ko);
            qah[ks][2] = *(const uint32_t*)(Qh0 + ko + 16);
            qah[ks][3] = *(const uint32_t*)(Qh0 + 8 * AT_PITCHB + ko + 16);
            qal[ks][0] = *(const uint32_t*)(Ql0 + ko);
            qal[ks][1] = *(const uint32_t*)(Ql0 + 8 * AT_PITCHB + ko);
            qal[ks][2] = *(const uint32_t*)(Ql0 + ko + 16);
            qal[ks][3] = *(const uint32_t*)(Ql0 + 8 * AT_PITCHB + ko + 16);
        }
    }

    float m0 = -1e30f, m1 = -1e30f, l0 = 0.f, l1 = 0.f;
    float o[8][4];
#pragma unroll
    for (int nt = 0; nt < 8; nt++)
#pragma unroll
        for (int e = 0; e < 4; e++) o[nt][e] = 0.f;

    for (int kt = 0; kt < SEQ / 64; kt++) {
        CP_WAIT1();
        __syncthreads();
        const char* stp = smem + AT_ST0 + (kt & 1) * AT_STSZ;

        // ---- S = Q @ K^T, bf16 3-pass ----
        float sc[8][4];
#pragma unroll
        for (int nt = 0; nt < 8; nt++)
#pragma unroll
            for (int e = 0; e < 4; e++) sc[nt][e] = 0.f;

#pragma unroll
        for (int ks = 0; ks < 4; ks++) {
            const int ko = ks * 32;
#pragma unroll
            for (int nt = 0; nt < 8; nt++) {
                const char* kp = stp + (nt * 8 + g) * AT_PITCHB + ko + 4 * t;
                uint32_t bhf[2], blf[2];
                bhf[0] = *(const uint32_t*)kp;
                bhf[1] = *(const uint32_t*)(kp + 16);
                blf[0] = *(const uint32_t*)(kp + AT_KARR);
                blf[1] = *(const uint32_t*)(kp + AT_KARR + 16);
                mma_bf16(sc[nt], qah[ks], bhf);
                mma_bf16(sc[nt], qal[ks], bhf);
                mma_bf16(sc[nt], qah[ks], blf);
            }
        }

        // ---- online softmax in registers ----
        float mx0 = -1e30f, mx1 = -1e30f;
#pragma unroll
        for (int nt = 0; nt < 8; nt++) {
            mx0 = fmaxf(mx0, fmaxf(sc[nt][0], sc[nt][1]));
            mx1 = fmaxf(mx1, fmaxf(sc[nt][2], sc[nt][3]));
        }
        mx0 = fmaxf(mx0, __shfl_xor_sync(0xffffffffu, mx0, 1));
        mx0 = fmaxf(mx0, __shfl_xor_sync(0xffffffffu, mx0, 2));
        mx1 = fmaxf(mx1, __shfl_xor_sync(0xffffffffu, mx1, 1));
        mx1 = fmaxf(mx1, __shfl_xor_sync(0xffffffffu, mx1, 2));
        const float mn0 = fmaxf(m0, mx0), mn1 = fmaxf(m1, mx1);
        const float a0 = __expf(m0 - mn0), a1 = __expf(m1 - mn1);
        float s0 = 0.f, s1 = 0.f;
#pragma unroll
        for (int nt = 0; nt < 8; nt++) {
            sc[nt][0] = __expf(sc[nt][0] - mn0); s0 += sc[nt][0];
            sc[nt][1] = __expf(sc[nt][1] - mn0); s0 += sc[nt][1];
            sc[nt][2] = __expf(sc[nt][2] - mn1); s1 += sc[nt][2];
            sc[nt][3] = __expf(sc[nt][3] - mn1); s1 += sc[nt][3];
        }
        s0 += __shfl_xor_sync(0xffffffffu, s0, 1);
        s0 += __shfl_xor_sync(0xffffffffu, s0, 2);
        s1 += __shfl_xor_sync(0xffffffffu, s1, 1);
        s1 += __shfl_xor_sync(0xffffffffu, s1, 2);
        l0 = l0 * a0 + s0;  m0 = mn0;
        l1 = l1 * a1 + s1;  m1 = mn1;
#pragma unroll
        for (int nt = 0; nt < 8; nt++) {
            o[nt][0] *= a0; o[nt][1] *= a0;
            o[nt][2] *= a1; o[nt][3] *= a1;
        }

        // ---- O += P @ V, single-pass fp16 ----
#pragma unroll
        for (int js = 0; js < 4; js++) {
            const int n0 = 2 * js, n1 = 2 * js + 1;
            uint32_t pa[4];
            pa[0] = packh2(sc[n0][0], sc[n0][1]);
            pa[1] = packh2(sc[n0][2], sc[n0][3]);
            pa[2] = packh2(sc[n1][0], sc[n1][1]);
            pa[3] = packh2(sc[n1][2], sc[n1][3]);
#pragma unroll
            for (int nt = 0; nt < 8; nt++) {
                const char* vp = stp + 2 * AT_KARR + (nt * 8 + g) * AT_PITCHB + js * 32 + 4 * t;
                uint32_t bv[2];
                bv[0] = *(const uint32_t*)vp;
                bv[1] = *(const uint32_t*)(vp + 16);
                mma_f16(o[nt], pa, bv);
            }
        }

        __syncthreads();
        if (kt + 2 < SEQ / 64) load_stage(kt & 1, kt + 2);
        else                   CP_COMMIT();
    }

    // ---- normalize, split to bf16 h/l, write out ----
    const float li0 = 1.f / l0, li1 = 1.f / l1;
    const int row0 = qt * 128 + wid * 16 + g;
#pragma unroll
    for (int nt = 0; nt < 8; nt++) {
        const int col = ho + nt * 8 + 2 * t;
        uint32_t h0, lo0, h1, lo1;
        packsplit2(o[nt][0] * li0, o[nt][1] * li0, h0, lo0);
        packsplit2(o[nt][2] * li1, o[nt][3] * li1, h1, lo1);
        *(uint32_t*)&g_xh[(size_t)row0 * 2048 + col]       = h0;
        *(uint32_t*)&g_xl[(size_t)row0 * 2048 + col]       = lo0;
        *(uint32_t*)&g_xh[(size_t)(row0 + 8) * 2048 + col] = h1;
        *(uint32_t*)&g_xl[(size_t)(row0 + 8) * 2048 + col] = lo1;
    }
}

// ---------------------------------------------------------------------------
// kernel_launch
// ---------------------------------------------------------------------------
extern "C" void kernel_launch(void* const* d_in, const int* in_sizes, int n_in,
                              void* d_out, int out_size)
{
    const float* query = (const float*)d_in[0];
    const float* key   = (const float*)d_in[1];
    const float* value = (const float*)d_in[2];
    const float* Wq    = (const float*)d_in[3];
    const float* bq    = (const float*)d_in[4];
    const float* Wk    = (const float*)d_in[5];
    const float* bk    = (const float*)d_in[6];
    const float* Wv    = (const float*)d_in[7];
    const float* bv    = (const float*)d_in[8];
    const float* Wo    = (const float*)d_in[9];
    const float* bo    = (const float*)d_in[10];
    float* out = (float*)d_out;

    cudaFuncSetAttribute(gemm_qkv_kernel,
                         cudaFuncAttributeMaxDynamicSharedMemorySize, GK_DSMEM);
    cudaFuncSetAttribute(gemm_o_kernel,
                         cudaFuncAttributeMaxDynamicSharedMemorySize, GK_DSMEM);
    cudaFuncSetAttribute(attn_mma_kernel,
                         cudaFuncAttributeMaxDynamicSharedMemorySize, AT_SMEM);

    split_inputs_kernel<<<dim3(NTOT / 1024, 3), 256>>>(query, key, value);
    split_weights_kernel<<<dim3(NW / 1024, 4), 256>>>(Wq, Wk, Wv, Wo);

    gemm_qkv_kernel<<<dim3(DIM / 128, MTOK / 128, 3), 256, GK_DSMEM>>>(bq, bk, bv);
    vsplit_transpose_kernel<<<dim3(SEQ / 64, BATCH * NH), 256>>>();

    attn_mma_kernel<<<dim3(SEQ / 128, BATCH * NH), 256, AT_SMEM>>>();

    gemm_o_kernel<<<dim3(DIM / 128, MTOK / 128), 256, GK_DSMEM>>>(bo, out);
}

// round 8
// speedup vs baseline: 2.1169x; 1.0166x over previous
#include <cuda_runtime.h>
#include <cuda_bf16.h>
#include <cuda_fp16.h>
#include <cstdint>

// Problem constants
#define SEQ   2048
#define BATCH 2
#define DIM   1024
#define NH    16
#define HD    64
#define MTOK  (SEQ * BATCH)   // 4096 tokens
#define NTOT  (MTOK * DIM)    // 4M elements
#define NW    (DIM * DIM)     // 1M weight elements

// Scratch (allocation-free rule: __device__ globals)
__device__ float g_v[NTOT];                       // V projection, fp32 (pre-transpose)
__device__ __nv_bfloat16 g_qih[NTOT], g_qil[NTOT];
__device__ __nv_bfloat16 g_kih[NTOT], g_kil[NTOT];
__device__ __nv_bfloat16 g_vih[NTOT], g_vil[NTOT];
__device__ __nv_bfloat16 g_wqh[NW], g_wql[NW];
__device__ __nv_bfloat16 g_wkh[NW], g_wkl[NW];
__device__ __nv_bfloat16 g_wvh[NW], g_wvl[NW];
__device__ __nv_bfloat16 g_woh[NW], g_wol[NW];
__device__ __nv_bfloat16 g_qh[NTOT], g_ql[NTOT];
__device__ __nv_bfloat16 g_kh[NTOT], g_kl[NTOT];
__device__ __half        g_vt[NTOT];              // V transposed [bh][d][s], fp16
__device__ __nv_bfloat16 g_xh[NTOT], g_xl[NTOT];

// ===========================================================================
// Helpers (family-safe PTX: cp.async, mma.sync, ldmatrix — no tcgen05)
// ===========================================================================
__device__ __forceinline__ uint32_t sm_u32(const void* p) {
    return (uint32_t)__cvta_generic_to_shared(p);
}
__device__ __forceinline__ void cp_async16(uint32_t smem_addr, const void* gptr) {
    asm volatile("cp.async.cg.shared.global [%0], [%1], 16;" :: "r"(smem_addr), "l"(gptr) : "memory");
}
#define CP_COMMIT() asm volatile("cp.async.commit_group;" ::: "memory")
#define CP_WAIT1()  asm volatile("cp.async.wait_group 1;" ::: "memory")
#define CP_WAIT2()  asm volatile("cp.async.wait_group 2;" ::: "memory")

__device__ __forceinline__ void mma_bf16(float* c, const uint32_t* a, const uint32_t* b) {
    asm volatile(
        "mma.sync.aligned.m16n8k16.row.col.f32.bf16.bf16.f32 "
        "{%0,%1,%2,%3}, {%4,%5,%6,%7}, {%8,%9}, {%0,%1,%2,%3};"
        : "+f"(c[0]), "+f"(c[1]), "+f"(c[2]), "+f"(c[3])
        : "r"(a[0]), "r"(a[1]), "r"(a[2]), "r"(a[3]), "r"(b[0]), "r"(b[1]));
}
__device__ __forceinline__ void mma_f16(float* c, const uint32_t* a, const uint32_t* b) {
    asm volatile(
        "mma.sync.aligned.m16n8k16.row.col.f32.f16.f16.f32 "
        "{%0,%1,%2,%3}, {%4,%5,%6,%7}, {%8,%9}, {%0,%1,%2,%3};"
        : "+f"(c[0]), "+f"(c[1]), "+f"(c[2]), "+f"(c[3])
        : "r"(a[0]), "r"(a[1]), "r"(a[2]), "r"(a[3]), "r"(b[0]), "r"(b[1]));
}
__device__ __forceinline__ void ldsm_x4(uint32_t* r, uint32_t addr) {
    asm volatile("ldmatrix.sync.aligned.m8n8.x4.shared.b16 {%0,%1,%2,%3}, [%4];"
                 : "=r"(r[0]), "=r"(r[1]), "=r"(r[2]), "=r"(r[3]) : "r"(addr));
}

__device__ __forceinline__ void packsplit2(float x, float y, uint32_t& h, uint32_t& l) {
    __nv_bfloat162 hb = __float22bfloat162_rn(make_float2(x, y));
    h = *reinterpret_cast<uint32_t*>(&hb);
    float rx = x - __low2float(hb);
    float ry = y - __high2float(hb);
    __nv_bfloat162 lb = __float22bfloat162_rn(make_float2(rx, ry));
    l = *reinterpret_cast<uint32_t*>(&lb);
}
__device__ __forceinline__ uint32_t packh2(float x, float y) {
    __half2 hp = __float22half2_rn(make_float2(x, y));
    return *reinterpret_cast<uint32_t*>(&hp);
}

// ===========================================================================
// Prep: one merged split kernel (inputs + weights run concurrently)
// ===========================================================================
__device__ __forceinline__ void split_body(const float* __restrict__ x,
                                           __nv_bfloat16* __restrict__ h,
                                           __nv_bfloat16* __restrict__ l)
{
    const int i4 = (blockIdx.x * 256 + threadIdx.x) * 4;
    float4 v = *(const float4*)(x + i4);
    uint32_t h0, l0, h1, l1;
    packsplit2(v.x, v.y, h0, l0);
    packsplit2(v.z, v.w, h1, l1);
    uint2 hh = {h0, h1}, ll = {l0, l1};
    *(uint2*)(h + i4) = hh;
    *(uint2*)(l + i4) = ll;
}

__global__ __launch_bounds__(256)
void split_all_kernel(const float* __restrict__ q, const float* __restrict__ k,
                      const float* __restrict__ v,
                      const float* __restrict__ wq, const float* __restrict__ wk,
                      const float* __restrict__ wv, const float* __restrict__ wo)
{
    const int y = blockIdx.y;
    if (y < 3) {
        const float* src = (y == 0) ? q : (y == 1) ? k : v;
        __nv_bfloat16* h = (y == 0) ? g_qih : (y == 1) ? g_kih : g_vih;
        __nv_bfloat16* l = (y == 0) ? g_qil : (y == 1) ? g_kil : g_vil;
        split_body(src, h, l);
    } else {
        if (blockIdx.x >= NW / 1024) return;
        const int w = y - 3;
        const float* src = (w == 0) ? wq : (w == 1) ? wk : (w == 2) ? wv : wo;
        __nv_bfloat16* h = (w == 0) ? g_wqh : (w == 1) ? g_wkh : (w == 2) ? g_wvh : g_woh;
        __nv_bfloat16* l = (w == 0) ? g_wql : (w == 1) ? g_wkl : (w == 2) ? g_wvl : g_wol;
        split_body(src, h, l);
    }
}

// V transpose + fp16: g_v[s][b*1024+h*64+d] -> g_vt[(bh*64+d)*2048 + s]
__global__ __launch_bounds__(256)
void vsplit_transpose_kernel()
{
    __shared__ float ts[64][65];
    const int st = blockIdx.x;
    const int bh = blockIdx.y;
    const int bb = bh >> 4, hh = bh & 15;
    const int tid = threadIdx.x;
    {
        const int r  = tid >> 2;
        const int c0 = (tid & 3) * 16;
        const float* src = g_v + (size_t)(st * 64 + r) * 2048 + bb * 1024 + hh * 64 + c0;
#pragma unroll
        for (int u = 0; u < 16; u += 4) {
            float4 t = *(const float4*)(src + u);
            ts[r][c0 + u + 0] = t.x; ts[r][c0 + u + 1] = t.y;
            ts[r][c0 + u + 2] = t.z; ts[r][c0 + u + 3] = t.w;
        }
    }
    __syncthreads();
    {
        const int d  = tid >> 2;
        const int s0 = (tid & 3) * 16;
        const size_t base = (size_t)(bh * 64 + d) * 2048 + st * 64 + s0;
#pragma unroll
        for (int u = 0; u < 16; u += 2)
            *(uint32_t*)(g_vt + base + u) = packh2(ts[s0 + u][d], ts[s0 + u + 1][d]);
    }
}

// ===========================================================================
// bf16 3-pass split GEMM core (unchanged from round 7, known-good)
// ===========================================================================
#define GK_PITCH 80
#define GK_ARR   (128 * GK_PITCH)
#define GK_STAGE (4 * GK_ARR)
#define GK_DSMEM (2 * GK_STAGE)        // 81920 bytes -> 2 CTAs/SM

__device__ __forceinline__ void gemm_core(
    const __nv_bfloat16* __restrict__ Xh, const __nv_bfloat16* __restrict__ Xl,
    const __nv_bfloat16* __restrict__ Wh, const __nv_bfloat16* __restrict__ Wl,
    const float* __restrict__ bias,
    float* __restrict__ Yf, __nv_bfloat16* __restrict__ Yh, __nv_bfloat16* __restrict__ Yl,
    int mode, char* smem)
{
    const uint32_t sb = sm_u32(smem);
    const int K = DIM, N = DIM;

    const int tid  = threadIdx.x;
    const int wid  = tid >> 5;
    const int lane = tid & 31;
    const int bm   = blockIdx.y;
    const int bn   = blockIdx.x;

    const int lrow = tid >> 1;
    const int lc0  = (tid & 1) * 2;

    auto load_chunk = [&](int st, int c) {
        const uint32_t stb = sb + st * GK_STAGE + lrow * GK_PITCH;
        const int k0 = c * 32;
        const __nv_bfloat16* s0 = Xh + (size_t)(bm * 128 + lrow) * K + k0;
        const __nv_bfloat16* s1 = Xl + (size_t)(bm * 128 + lrow) * K + k0;
        const __nv_bfloat16* s2 = Wh + (size_t)(bn * 128 + lrow) * K + k0;
        const __nv_bfloat16* s3 = Wl + (size_t)(bn * 128 + lrow) * K + k0;
#pragma unroll
        for (int i = 0; i < 2; i++) {
            const int ch = lc0 + i;
            const uint32_t off = (uint32_t)(ch << 4);
            cp_async16(stb + 0 * GK_ARR + off, s0 + ch * 8);
            cp_async16(stb + 1 * GK_ARR + off, s1 + ch * 8);
            cp_async16(stb + 2 * GK_ARR + off, s2 + ch * 8);
            cp_async16(stb + 3 * GK_ARR + off, s3 + ch * 8);
        }
        CP_COMMIT();
    };

    load_chunk(0, 0);
    load_chunk(1, 1);

    const int wm = (wid & 1) * 64;
    const int wn = (wid >> 1) * 32;
    const int g  = lane >> 2;
    const int t  = lane & 3;
    const int a_row = (lane & 7) + ((lane >> 3) & 1) * 8;
    const int a_chi = lane >> 4;
    const int b_row = (lane & 7) + ((lane >> 4) & 1) * 8;
    const int b_chi = (lane >> 3) & 1;

    float acc[4][4][4];
#pragma unroll
    for (int mt = 0; mt < 4; mt++)
#pragma unroll
        for (int nt = 0; nt < 4; nt++)
#pragma unroll
            for (int e = 0; e < 4; e++) acc[mt][nt][e] = 0.f;

    for (int c = 0; c < 32; c++) {
        CP_WAIT1();
        __syncthreads();
        const uint32_t stb = sb + (c & 1) * GK_STAGE;

#pragma unroll
        for (int ks = 0; ks < 2; ks++) {
            uint32_t Ah[4][4], Al[4][4], Bh[2][4], Bl[2][4];
#pragma unroll
            for (int mt = 0; mt < 4; mt++) {
                const uint32_t ro = (uint32_t)((wm + mt * 16 + a_row) * GK_PITCH
                                  + ((ks * 2 + a_chi) << 4));
                ldsm_x4(Ah[mt], stb + 0 * GK_ARR + ro);
                ldsm_x4(Al[mt], stb + 1 * GK_ARR + ro);
            }
#pragma unroll
            for (int p = 0; p < 2; p++) {
                const uint32_t ro = (uint32_t)((wn + p * 16 + b_row) * GK_PITCH
                                  + ((ks * 2 + b_chi) << 4));
                ldsm_x4(Bh[p], stb + 2 * GK_ARR + ro);
                ldsm_x4(Bl[p], stb + 3 * GK_ARR + ro);
            }
#pragma unroll
            for (int mt = 0; mt < 4; mt++)
#pragma unroll
                for (int nt = 0; nt < 4; nt++) {
                    const int p = nt >> 1, s2 = (nt & 1) * 2;
                    uint32_t bh[2] = {Bh[p][s2], Bh[p][s2 + 1]};
                    uint32_t bl[2] = {Bl[p][s2], Bl[p][s2 + 1]};
                    mma_bf16(acc[mt][nt], Ah[mt], bh);
                    mma_bf16(acc[mt][nt], Al[mt], bh);
                    mma_bf16(acc[mt][nt], Ah[mt], bl);
                }
        }

        __syncthreads();
        if (c + 2 < 32) load_chunk(c & 1, c + 2);
        else            CP_COMMIT();
    }

#pragma unroll
    for (int mt = 0; mt < 4; mt++) {
        const int row = bm * 128 + wm + mt * 16 + g;
#pragma unroll
        for (int nt = 0; nt < 4; nt++) {
            const int col = bn * 128 + wn + nt * 8 + 2 * t;
            float2 bi = *(const float2*)&bias[col];
            const float c0 = acc[mt][nt][0] + bi.x;
            const float c1 = acc[mt][nt][1] + bi.y;
            const float c2 = acc[mt][nt][2] + bi.x;
            const float c3 = acc[mt][nt][3] + bi.y;
            if (mode == 0) {
                float2 r01 = {c0, c1}, r23 = {c2, c3};
                *(float2*)&Yf[(size_t)row * N + col]       = r01;
                *(float2*)&Yf[(size_t)(row + 8) * N + col] = r23;
            } else {
                uint32_t h0, l0, h1, l1;
                packsplit2(c0, c1, h0, l0);
                packsplit2(c2, c3, h1, l1);
                *(uint32_t*)&Yh[(size_t)row * N + col]       = h0;
                *(uint32_t*)&Yl[(size_t)row * N + col]       = l0;
                *(uint32_t*)&Yh[(size_t)(row + 8) * N + col] = h1;
                *(uint32_t*)&Yl[(size_t)(row + 8) * N + col] = l1;
            }
        }
    }
}

__global__ __launch_bounds__(256, 2)
void gemm_qkv_kernel(const float* __restrict__ bq, const float* __restrict__ bk,
                     const float* __restrict__ bv)
{
    extern __shared__ char smem[];
    const int z = blockIdx.z;
    if (z == 0)      gemm_core(g_qih, g_qil, g_wqh, g_wql, bq, nullptr, g_qh, g_ql, 1, smem);
    else if (z == 1) gemm_core(g_kih, g_kil, g_wkh, g_wkl, bk, nullptr, g_kh, g_kl, 1, smem);
    else             gemm_core(g_vih, g_vil, g_wvh, g_wvl, bv, g_v, nullptr, nullptr, 0, smem);
}

__global__ __launch_bounds__(256, 2)
void gemm_o_kernel(const float* __restrict__ bo, float* __restrict__ out)
{
    extern __shared__ char smem[];
    gemm_core(g_xh, g_xl, g_woh, g_wol, bo, out, nullptr, nullptr, 0, smem);
}

// ===========================================================================
// Flash attention: QK^T bf16 3-pass, PV fp16 single-pass, fp32 accum.
// Fragments via ldmatrix.x4 (K, V); Q hoisted to registers.
// ===========================================================================
#define AT_PITCHB 144
#define AT_QBYTES (128 * AT_PITCHB)        // 18432 per Q array
#define AT_KARR   (64 * AT_PITCHB)         // 9216
#define AT_ST0    (2 * AT_QBYTES)          // 36864
#define AT_STSZ   (3 * AT_KARR)            // 27648: KH, KL, VT
#define AT_SMEM   (AT_ST0 + 2 * AT_STSZ)   // 92160 bytes -> 2 CTAs/SM

__global__ __launch_bounds__(256, 2)
void attn_mma_kernel()
{
    extern __shared__ char smem[];
    const uint32_t sbase = sm_u32(smem);

    const int tid  = threadIdx.x;
    const int wid  = tid >> 5;
    const int lane = tid & 31;
    const int g    = lane >> 2;
    const int t    = lane & 3;
    const int b_row = (lane & 7) + ((lane >> 4) & 1) * 8;
    const int b_chi = (lane >> 3) & 1;
    const int qt   = blockIdx.x;
    const int bh   = blockIdx.y;
    const int bb   = bh >> 4, hh = bh & 15;
    const int ho   = bb * 1024 + hh * 64;

    // ---- Q tile load ----
    {
        const int r  = tid >> 1;
        const int c0 = (tid & 1) * 4;
        const __nv_bfloat16* sh = g_qh + (size_t)(qt * 128 + r) * 2048 + ho + c0 * 8;
        const __nv_bfloat16* sl = g_ql + (size_t)(qt * 128 + r) * 2048 + ho + c0 * 8;
        const uint32_t dh = sbase + r * AT_PITCHB + c0 * 16;
        const uint32_t dl = dh + AT_QBYTES;
#pragma unroll
        for (int i = 0; i < 4; i++) {
            cp_async16(dh + i * 16, sh + i * 8);
            cp_async16(dl + i * 16, sl + i * 8);
        }
        CP_COMMIT();
    }

    auto load_stage = [&](int s, int kt) {
        const uint32_t stb = sbase + AT_ST0 + s * AT_STSZ;
        const int which = tid >> 6;
        const int r = tid & 63;
        if (which < 2) {
            const __nv_bfloat16* src = (which == 0 ? g_kh : g_kl)
                                     + (size_t)(kt * 64 + r) * 2048 + ho;
            const uint32_t dst = stb + which * AT_KARR + r * AT_PITCHB;
#pragma unroll
            for (int i = 0; i < 8; i++) cp_async16(dst + i * 16, src + i * 8);
        } else {
            const int half = which - 2;
            const __half* src = g_vt + (size_t)(bh * 64 + r) * 2048 + kt * 64 + half * 32;
            const uint32_t dst = stb + 2 * AT_KARR + r * AT_PITCHB + half * 64;
#pragma unroll
            for (int i = 0; i < 4; i++) cp_async16(dst + i * 16, src + i * 8);
        }
        CP_COMMIT();
    };

    load_stage(0, 0);
    load_stage(1, 1);

    // Q group done -> hoist Q fragments to registers
    CP_WAIT2();
    __syncthreads();
    uint32_t qah[4][4], qal[4][4];
    {
        const char* Qh0 = smem + (wid * 16 + g) * AT_PITCHB + 4 * t;
        const char* Ql0 = Qh0 + AT_QBYTES;
#pragma unroll
        for (int ks = 0; ks < 4; ks++) {
            const int ko = ks * 32;
            qah[ks][0] = *(const uint32_t*)(Qh0 + ko);
            qah[ks][1] = *(const uint32_t*)(Qh0 + 8 * AT_PITCHB + ko);
            qah[ks][2] = *(const uint32_t*)(Qh0 + ko + 16);
            qah[ks][3] = *(const uint32_t*)(Qh0 + 8 * AT_PITCHB + ko + 16);
            qal[ks][0] = *(const uint32_t*)(Ql0 + ko);
            qal[ks][1] = *(const uint32_t*)(Ql0 + 8 * AT_PITCHB + ko);
            qal[ks][2] = *(const uint32_t*)(Ql0 + ko + 16);
            qal[ks][3] = *(const uint32_t*)(Ql0 + 8 * AT_PITCHB + ko + 16);
        }
    }

    float m0 = -1e30f, m1 = -1e30f, l0 = 0.f, l1 = 0.f;
    float o[8][4];
#pragma unroll
    for (int nt = 0; nt < 8; nt++)
#pragma unroll
        for (int e = 0; e < 4; e++) o[nt][e] = 0.f;

    for (int kt = 0; kt < SEQ / 64; kt++) {
        CP_WAIT1();
        __syncthreads();
        const uint32_t stpu = sbase + AT_ST0 + (kt & 1) * AT_STSZ;

        // ---- S = Q @ K^T, bf16 3-pass, K frags via ldmatrix ----
        float sc[8][4];
#pragma unroll
        for (int nt = 0; nt < 8; nt++)
#pragma unroll
            for (int e = 0; e < 4; e++) sc[nt][e] = 0.f;

#pragma unroll
        for (int ks = 0; ks < 4; ks++) {
#pragma unroll
            for (int p = 0; p < 4; p++) {
                const uint32_t ro = (uint32_t)((p * 16 + b_row) * AT_PITCHB
                                  + ((ks * 2 + b_chi) << 4));
                uint32_t Bh[4], Bl[4];
                ldsm_x4(Bh, stpu + ro);
                ldsm_x4(Bl, stpu + AT_KARR + ro);
#pragma unroll
                for (int ntl = 0; ntl < 2; ntl++) {
                    const int nt = p * 2 + ntl;
                    uint32_t bhf[2] = {Bh[ntl * 2], Bh[ntl * 2 + 1]};
                    uint32_t blf[2] = {Bl[ntl * 2], Bl[ntl * 2 + 1]};
                    mma_bf16(sc[nt], qah[ks], bhf);
                    mma_bf16(sc[nt], qal[ks], bhf);
                    mma_bf16(sc[nt], qah[ks], blf);
                }
            }
        }

        // ---- online softmax in registers ----
        float mx0 = -1e30f, mx1 = -1e30f;
#pragma unroll
        for (int nt = 0; nt < 8; nt++) {
            mx0 = fmaxf(mx0, fmaxf(sc[nt][0], sc[nt][1]));
            mx1 = fmaxf(mx1, fmaxf(sc[nt][2], sc[nt][3]));
        }
        mx0 = fmaxf(mx0, __shfl_xor_sync(0xffffffffu, mx0, 1));
        mx0 = fmaxf(mx0, __shfl_xor_sync(0xffffffffu, mx0, 2));
        mx1 = fmaxf(mx1, __shfl_xor_sync(0xffffffffu, mx1, 1));
        mx1 = fmaxf(mx1, __shfl_xor_sync(0xffffffffu, mx1, 2));
        const float mn0 = fmaxf(m0, mx0), mn1 = fmaxf(m1, mx1);
        const float a0 = __expf(m0 - mn0), a1 = __expf(m1 - mn1);
        float s0 = 0.f, s1 = 0.f;
#pragma unroll
        for (int nt = 0; nt < 8; nt++) {
            sc[nt][0] = __expf(sc[nt][0] - mn0); s0 += sc[nt][0];
            sc[nt][1] = __expf(sc[nt][1] - mn0); s0 += sc[nt][1];
            sc[nt][2] = __expf(sc[nt][2] - mn1); s1 += sc[nt][2];
            sc[nt][3] = __expf(sc[nt][3] - mn1); s1 += sc[nt][3];
        }
        s0 += __shfl_xor_sync(0xffffffffu, s0, 1);
        s0 += __shfl_xor_sync(0xffffffffu, s0, 2);
        s1 += __shfl_xor_sync(0xffffffffu, s1, 1);
        s1 += __shfl_xor_sync(0xffffffffu, s1, 2);
        l0 = l0 * a0 + s0;  m0 = mn0;
        l1 = l1 * a1 + s1;  m1 = mn1;
#pragma unroll
        for (int nt = 0; nt < 8; nt++) {
            o[nt][0] *= a0; o[nt][1] *= a0;
            o[nt][2] *= a1; o[nt][3] *= a1;
        }

        // ---- O += P @ V, fp16 single-pass, V frags via ldmatrix ----
#pragma unroll
        for (int js = 0; js < 4; js++) {
            const int n0 = 2 * js, n1 = 2 * js + 1;
            uint32_t pa[4];
            pa[0] = packh2(sc[n0][0], sc[n0][1]);
            pa[1] = packh2(sc[n0][2], sc[n0][3]);
            pa[2] = packh2(sc[n1][0], sc[n1][1]);
            pa[3] = packh2(sc[n1][2], sc[n1][3]);
#pragma unroll
            for (int p = 0; p < 4; p++) {
                const uint32_t ro = (uint32_t)(2 * AT_KARR + (p * 16 + b_row) * AT_PITCHB
                                  + ((js * 2 + b_chi) << 4));
                uint32_t Bv[4];
                ldsm_x4(Bv, stpu + ro);
                uint32_t bv0[2] = {Bv[0], Bv[1]};
                uint32_t bv1[2] = {Bv[2], Bv[3]};
                mma_f16(o[p * 2],     pa, bv0);
                mma_f16(o[p * 2 + 1], pa, bv1);
            }
        }

        __syncthreads();
        if (kt + 2 < SEQ / 64) load_stage(kt & 1, kt + 2);
        else                   CP_COMMIT();
    }

    // ---- normalize, split to bf16 h/l, write out ----
    const float li0 = 1.f / l0, li1 = 1.f / l1;
    const int row0 = qt * 128 + wid * 16 + g;
#pragma unroll
    for (int nt = 0; nt < 8; nt++) {
        const int col = ho + nt * 8 + 2 * t;
        uint32_t h0, lo0, h1, lo1;
        packsplit2(o[nt][0] * li0, o[nt][1] * li0, h0, lo0);
        packsplit2(o[nt][2] * li1, o[nt][3] * li1, h1, lo1);
        *(uint32_t*)&g_xh[(size_t)row0 * 2048 + col]       = h0;
        *(uint32_t*)&g_xl[(size_t)row0 * 2048 + col]       = lo0;
        *(uint32_t*)&g_xh[(size_t)(row0 + 8) * 2048 + col] = h1;
        *(uint32_t*)&g_xl[(size_t)(row0 + 8) * 2048 + col] = lo1;
    }
}

// ---------------------------------------------------------------------------
// kernel_launch
// ---------------------------------------------------------------------------
extern "C" void kernel_launch(void* const* d_in, const int* in_sizes, int n_in,
                              void* d_out, int out_size)
{
    const float* query = (const float*)d_in[0];
    const float* key   = (const float*)d_in[1];
    const float* value = (const float*)d_in[2];
    const float* Wq    = (const float*)d_in[3];
    const float* bq    = (const float*)d_in[4];
    const float* Wk    = (const float*)d_in[5];
    const float* bk    = (const float*)d_in[6];
    const float* Wv    = (const float*)d_in[7];
    const float* bv    = (const float*)d_in[8];
    const float* Wo    = (const float*)d_in[9];
    const float* bo    = (const float*)d_in[10];
    float* out = (float*)d_out;

    cudaFuncSetAttribute(gemm_qkv_kernel,
                         cudaFuncAttributeMaxDynamicSharedMemorySize, GK_DSMEM);
    cudaFuncSetAttribute(gemm_o_kernel,
                         cudaFuncAttributeMaxDynamicSharedMemorySize, GK_DSMEM);
    cudaFuncSetAttribute(attn_mma_kernel,
                         cudaFuncAttributeMaxDynamicSharedMemorySize, AT_SMEM);

    split_all_kernel<<<dim3(NTOT / 1024, 7), 256>>>(query, key, value, Wq, Wk, Wv, Wo);

    gemm_qkv_kernel<<<dim3(DIM / 128, MTOK / 128, 3), 256, GK_DSMEM>>>(bq, bk, bv);
    vsplit_transpose_kernel<<<dim3(SEQ / 64, BATCH * NH), 256>>>();

    attn_mma_kernel<<<dim3(SEQ / 128, BATCH * NH), 256, AT_SMEM>>>();

    gemm_o_kernel<<<dim3(DIM / 128, MTOK / 128), 256, GK_DSMEM>>>(bo, out);
}